// round 9
// baseline (speedup 1.0000x reference)
#include <cuda_runtime.h>
#include <cuda.h>
#include <cuda_bf16.h>
#include <math.h>
#include <stdint.h>

// Problem constants
#define B_   128
#define S_   256
#define D_   1024
#define K_   8

// -------- scratch (no allocations allowed) --------
__device__ uint16_t g_Wb [(size_t)192 * D_];    // packed weights q|k|v, bf16
__device__ uint16_t g_Xp [(size_t)512 * D_];    // pooled rows bf16: row = bs*2+{max,avg}
__device__ float    g_Yqkv[(size_t)4096 * 192]; // qkv projections

__device__ __forceinline__ uint2 f4_to_bf4(float4 v) {
    __nv_bfloat162 lo = __floats2bfloat162_rn(v.x, v.y);
    __nv_bfloat162 hi = __floats2bfloat162_rn(v.z, v.w);
    uint2 r;
    r.x = *reinterpret_cast<uint32_t*>(&lo);
    r.y = *reinterpret_cast<uint32_t*>(&hi);
    return r;
}

// =====================================================================
// Kernel 1: pack q|k|v weights (192 rows x 1024) f32 -> bf16
// =====================================================================
__global__ void __launch_bounds__(512)
wpack_kernel(const float* __restrict__ wq, const float* __restrict__ wk,
             const float* __restrict__ wv)
{
    int f4base = blockIdx.x * 2048 + threadIdx.x;
    #pragma unroll
    for (int i = 0; i < 4; i++) {
        int f4 = f4base + i * 512;           // 0..49151
        int wsel = f4 >> 14;                 // 16384 f4 per matrix
        const float* W = (wsel == 0) ? wq : (wsel == 1) ? wk : wv;
        float4 v = reinterpret_cast<const float4*>(W)[f4 & 16383];
        reinterpret_cast<uint2*>(g_Wb)[f4] = f4_to_bf4(v);
    }
}

// =====================================================================
// Kernel 2: FUSED gather + bf16 mma.sync GEMM (+ pooling on by==2)
// grid 384 CTAs: bx = cta/3 (row tile of 32 = 2 bs), by = cta%3 (q/k/v).
// A: gathered from token per stage (LDG f32 -> bf16 swizzled STS, reg dbuf)
// W: TMA SW128 4-stage ring from g_Wb.
// =====================================================================
#define W_ST   8192
#define NST    4
#define A_BUF  4096
#define GEMM_SMEM (2 * A_BUF + NST * W_ST)   // 40960

__device__ __forceinline__ void mbar_wait(uint32_t mbar, int phase) {
    asm volatile(
        "{\n\t.reg .pred P;\n"
        "W%=:\n\t"
        "mbarrier.try_wait.parity.acquire.cta.shared::cta.b64 P, [%0], %1, 0x989680;\n\t"
        "@P bra D%=;\n\t"
        "bra W%=;\n"
        "D%=:\n\t}"
        :: "r"(mbar), "r"(phase) : "memory");
}

__device__ __forceinline__ void tma_2d(uint32_t dst, const CUtensorMap* tm,
                                       int x, int y, uint32_t mbar) {
    asm volatile(
        "cp.async.bulk.tensor.2d.shared::cta.global.tile.mbarrier::complete_tx::bytes "
        "[%0], [%1, {%2, %3}], [%4];"
        :: "r"(dst), "l"(tm), "r"(x), "r"(y), "r"(mbar) : "memory");
}

__global__ void __launch_bounds__(128, 2)
fused_kernel(const __grid_constant__ CUtensorMap tmW,
             const float* __restrict__ token,
             const int* __restrict__ kw_idx)
{
    extern __shared__ __align__(1024) uint16_t smem_b[];
    __shared__ __align__(8) uint64_t mbar_s[2 * NST];  // full[0..3], empty[0..3]
    __shared__ uint32_t rowOff[32];                    // token element offsets

    const uint32_t smem_s = (uint32_t)__cvta_generic_to_shared(smem_b);
    const uint32_t mb     = (uint32_t)__cvta_generic_to_shared(mbar_s);
    char* smem_raw = reinterpret_cast<char*>(smem_b);

    const int cta = blockIdx.x;
    const int bx  = cta / 3;
    const int by  = cta - bx * 3;
    const int tid = threadIdx.x;
    const int lane = tid & 31;
    const int wn   = tid >> 5;
    const int m0   = bx * 32;
    const int nW   = by * 64;

    // per-row token offsets (rows 0..31 = bs0 rows 0..15, bs1 rows 0..15)
    if (tid < 32) {
        int r  = tid & 15;
        int bs = bx * 2 + (tid >> 4);
        int b  = bs >> 1, s = bs & 1;
        int l  = r >> 3, k = r & 7;
        int idx = kw_idx[(b * 2 + (1 - s)) * K_ + k];
        rowOff[tid] = (uint32_t)((((b * 2 + s) * 2 + l) * S_ + idx) * D_);
    }
    if (tid == 0) {
        #pragma unroll
        for (int s = 0; s < NST; s++) {
            asm volatile("mbarrier.init.shared.b64 [%0], %1;"
                         :: "r"(mb + s * 8), "r"(1) : "memory");
            asm volatile("mbarrier.init.shared.b64 [%0], %1;"
                         :: "r"(mb + (NST + s) * 8), "r"(128) : "memory");
        }
    }
    __syncthreads();

    // A loader mapping: row = tid>>2, 4 float4 cols (tid&3)+4i
    const int arow = tid >> 2;
    const int aq   = tid & 3;
    const float* rowBase = token + rowOff[arow];
    const int asw = arow & 7;

    // stage A(kt) regs -> smem buf (bf16, XOR swizzle)
    #define A_STS(kt, pre) { \
        char* ab = smem_raw + ((kt) & 1) * A_BUF + arow * 128; \
        _Pragma("unroll") \
        for (int i = 0; i < 4; i++) { \
            int j = aq + i * 4; \
            uint32_t off = (((j >> 1) ^ asw) << 4) + ((j & 1) << 3); \
            *reinterpret_cast<uint2*>(ab + off) = f4_to_bf4((pre)[i]); \
        } \
    }
    #define A_LDG(kt, pre) { \
        const float4* src = reinterpret_cast<const float4*>(rowBase + (kt) * 64); \
        _Pragma("unroll") \
        for (int i = 0; i < 4; i++) (pre)[i] = src[aq + i * 4]; \
    }

    float4 pre[4];
    A_LDG(0, pre);
    A_STS(0, pre);
    A_LDG(1, pre);

    if (tid == 0) {
        #pragma unroll
        for (int s = 0; s < NST; s++) {
            uint32_t fb = mb + s * 8;
            asm volatile("mbarrier.arrive.expect_tx.shared.b64 _, [%0], %1;"
                         :: "r"(fb), "r"(W_ST) : "memory");
            tma_2d(smem_s + 2 * A_BUF + s * W_ST, &tmW, s * 64, nW, fb);
        }
    }
    __syncthreads();

    float c[2][2][4];
    #pragma unroll
    for (int i = 0; i < 2; i++)
        #pragma unroll
        for (int j = 0; j < 2; j++)
            #pragma unroll
            for (int r = 0; r < 4; r++) c[i][j][r] = 0.f;

    // ldmatrix geometry
    const int j4   = lane >> 3;
    const int lr   = lane & 7;
    const int aRow = (j4 & 1) * 8 + lr;
    const int aKj  = j4 >> 1;
    const int aSw  = aRow & 7;
    const int bRow = wn * 16 + (j4 >> 1) * 8 + lr;
    const int bKj  = j4 & 1;
    const int bSw  = bRow & 7;
    const uint32_t aByte0 = aRow * 128;
    const uint32_t aByte1 = (aRow + 16) * 128;
    const uint32_t bByte  = bRow * 128;

    // pooling lane mapping (by==2 only)
    const int pc  = tid & 63;
    const int bsl = tid >> 6;

    for (int kt = 0; kt < 16; kt++) {
        const int st = kt & 3;
        const int ph = (kt >> 2) & 1;
        mbar_wait(mb + st * 8, ph);

        const uint32_t As = smem_s + (kt & 1) * A_BUF;
        const uint32_t Bs = smem_s + 2 * A_BUF + st * W_ST;

        #pragma unroll
        for (int step = 0; step < 4; step++) {
            const int cA = (2 * step + aKj) ^ aSw;
            const int cB = (2 * step + bKj) ^ bSw;
            uint32_t a0[4], a1[4], bb[4];
            {
                uint32_t addr = As + aByte0 + (cA << 4);
                asm volatile("ldmatrix.sync.aligned.m8n8.x4.shared.b16 {%0,%1,%2,%3}, [%4];"
                             : "=r"(a0[0]), "=r"(a0[1]), "=r"(a0[2]), "=r"(a0[3]) : "r"(addr));
            }
            {
                uint32_t addr = As + aByte1 + (cA << 4);
                asm volatile("ldmatrix.sync.aligned.m8n8.x4.shared.b16 {%0,%1,%2,%3}, [%4];"
                             : "=r"(a1[0]), "=r"(a1[1]), "=r"(a1[2]), "=r"(a1[3]) : "r"(addr));
            }
            {
                uint32_t addr = Bs + bByte + (cB << 4);
                asm volatile("ldmatrix.sync.aligned.m8n8.x4.shared.b16 {%0,%1,%2,%3}, [%4];"
                             : "=r"(bb[0]), "=r"(bb[1]), "=r"(bb[2]), "=r"(bb[3]) : "r"(addr));
            }
            #pragma unroll
            for (int mt = 0; mt < 2; mt++) {
                const uint32_t* a = mt ? a1 : a0;
                #pragma unroll
                for (int nt = 0; nt < 2; nt++) {
                    asm volatile(
                        "mma.sync.aligned.m16n8k16.row.col.f32.bf16.bf16.f32 "
                        "{%0,%1,%2,%3}, {%4,%5,%6,%7}, {%8,%9}, {%0,%1,%2,%3};"
                        : "+f"(c[mt][nt][0]), "+f"(c[mt][nt][1]),
                          "+f"(c[mt][nt][2]), "+f"(c[mt][nt][3])
                        : "r"(a[0]), "r"(a[1]), "r"(a[2]), "r"(a[3]),
                          "r"(bb[nt*2]), "r"(bb[nt*2+1]));
                }
            }
        }

        asm volatile("mbarrier.arrive.shared.b64 _, [%0];"
                     :: "r"(mb + (NST + st) * 8) : "memory");

        // pooling (by==2): column max/mean over this stage's 16 rows per bs
        if (by == 2) {
            const char* ab = smem_raw + (kt & 1) * A_BUF;
            float mx = -3.4e38f, sm = 0.f;
            #pragma unroll
            for (int r16 = 0; r16 < 16; r16++) {
                int row = bsl * 16 + r16;
                uint32_t off = row * 128 + ((((pc >> 3) ^ (row & 7))) << 4) + (pc & 7) * 2;
                uint16_t raw = *reinterpret_cast<const uint16_t*>(ab + off);
                float v = __bfloat162float(__ushort_as_bfloat16(raw));
                mx = fmaxf(mx, v); sm += v;
            }
            int bs = bx * 2 + bsl;
            g_Xp[(size_t)(bs * 2 + 0) * D_ + kt * 64 + pc] =
                __bfloat16_as_ushort(__float2bfloat16_rn(mx));
            g_Xp[(size_t)(bs * 2 + 1) * D_ + kt * 64 + pc] =
                __bfloat16_as_ushort(__float2bfloat16_rn(sm * (1.f/16.f)));
        }

        if (kt < 15) {
            A_STS(kt + 1, pre);
            if (kt < 14) { A_LDG(kt + 2, pre); }
        }

        if (tid == 0 && kt + NST < 16) {
            mbar_wait(mb + (NST + st) * 8, ph);
            uint32_t fb = mb + st * 8;
            asm volatile("mbarrier.arrive.expect_tx.shared.b64 _, [%0], %1;"
                         :: "r"(fb), "r"(W_ST) : "memory");
            tma_2d(smem_s + 2 * A_BUF + st * W_ST, &tmW, (kt + NST) * 64, nW, fb);
        }
        __syncthreads();
    }

    // epilogue
    const int g  = lane >> 2;
    const int tg = lane & 3;
    #pragma unroll
    for (int mt = 0; mt < 2; mt++) {
        const int rA = m0 + mt * 16 + g;
        #pragma unroll
        for (int nt = 0; nt < 2; nt++) {
            const int col = by * 64 + wn * 16 + nt * 8 + 2 * tg;
            *reinterpret_cast<float2*>(g_Yqkv + (size_t)rA * 192 + col) =
                make_float2(c[mt][nt][0], c[mt][nt][1]);
            *reinterpret_cast<float2*>(g_Yqkv + (size_t)(rA + 8) * 192 + col) =
                make_float2(c[mt][nt][2], c[mt][nt][3]);
        }
    }
}

// =====================================================================
// Kernel 3: per-b heads (incl. inline mi projection). grid B_, 256 thr.
// =====================================================================
__device__ __forceinline__ float gelu_f(float x) {
    return 0.5f * x * (1.0f + erff(x * 0.70710678118654752440f));
}

__global__ void __launch_bounds__(256)
head_kernel(const float* __restrict__ q_b, const float* __restrict__ k_b,
            const float* __restrict__ v_b,
            const float* __restrict__ mi_w, const float* __restrict__ mi_b,
            const float* __restrict__ inter_w, const float* __restrict__ inter_b,
            const float* __restrict__ fc0_w, const float* __restrict__ fc0_b,
            const float* __restrict__ fc1_w, const float* __restrict__ fc1_b,
            float* __restrict__ out)
{
    __shared__ float q0[1024], k0[1024], v0[1024];
    __shared__ float q1[1024], k1[1024], v1[1024];
    __shared__ __align__(16) float pool[4][1024];
    __shared__ float att[512];
    __shared__ float e1s[1024], e2s[1024];
    __shared__ float sv[4][64];
    __shared__ float aV[256];
    __shared__ float feat[516];
    __shared__ float h1[64];

    int b = blockIdx.x;
    int tid = threadIdx.x;
    const float* Y0 = g_Yqkv + (size_t)(b * 2 + 0) * 16 * 192;
    const float* Y1 = g_Yqkv + (size_t)(b * 2 + 1) * 16 * 192;

    for (int t = tid; t < 1024; t += 256) {
        int n = t >> 6, h = t & 63;
        q0[t] = Y0[n * 192 +       h] + q_b[h];
        k0[t] = Y0[n * 192 +  64 + h] + k_b[h];
        v0[t] = Y0[n * 192 + 128 + h] + v_b[h];
        q1[t] = Y1[n * 192 +       h] + q_b[h];
        k1[t] = Y1[n * 192 +  64 + h] + k_b[h];
        v1[t] = Y1[n * 192 + 128 + h] + v_b[h];
    }
    // pooled rows: g_Xp row b*4 + i  (i: s1max, s1avg, s2max, s2avg)
    for (int t = tid; t < 4096; t += 256) {
        int i = t >> 10, c = t & 1023;
        pool[i][c] = __bfloat162float(
            __ushort_as_bfloat16(g_Xp[(size_t)(b * 4 + i) * 1024 + c]));
    }
    __syncthreads();

    // inline mi projection: sv[i][j] = mi_b[j] + pool[i] . mi_w[j]
    {
        int i = tid >> 6, j = tid & 63;
        float s = mi_b[j];
        const float4* w = reinterpret_cast<const float4*>(mi_w + (size_t)j * 1024);
        const float4* p = reinterpret_cast<const float4*>(pool[i]);
        #pragma unroll 4
        for (int q = 0; q < 256; q++) {
            float4 wv = w[q];
            float4 pv = p[q];
            s += pv.x * wv.x + pv.y * wv.y + pv.z * wv.z + pv.w * wv.w;
        }
        sv[i][j] = s;
    }

    for (int e = tid; e < 512; e += 256) {
        int which = e >> 8, n = (e >> 4) & 15, m = e & 15;
        const float* qq = which ? q1 : q0;
        const float* kk = which ? k0 : k1;
        float s = 0.f;
        #pragma unroll
        for (int h = 0; h < 64; h++) s += qq[n * 64 + h] * kk[m * 64 + h];
        att[e] = s * 0.125f;
    }
    __syncthreads();

    for (int e = tid; e < 2048; e += 256) {
        int which = e >> 10, n = (e >> 6) & 15, h = e & 63;
        const float* vv = which ? v0 : v1;
        float s = 0.f;
        #pragma unroll
        for (int m = 0; m < 16; m++) s += att[which * 256 + n * 16 + m] * vv[m * 64 + h];
        (which ? e2s : e1s)[n * 64 + h] = s;
    }
    __syncthreads();

    if (tid < 128) {
        int which = tid >> 6, hh = tid & 63;
        const float* E = which ? e2s : e1s;
        float mx = -3.4e38f, sm = 0.f;
        #pragma unroll
        for (int n = 0; n < 16; n++) { float v = E[n * 64 + hh]; mx = fmaxf(mx, v); sm += v; }
        feat[which * 128 + hh]      = mx;
        feat[which * 128 + 64 + hh] = sm * (1.f / 16.f);
    }

    {
        int i = tid >> 6, j = tid & 63;
        const float* src = sv[i >> 1];
        float s = inter_b[i * 64 + j];
        const float* wrow = inter_w + ((size_t)i * 64 + j) * 64;
        #pragma unroll
        for (int h = 0; h < 64; h++) s += wrow[h] * src[h];
        aV[i * 64 + j] = s;
    }
    __syncthreads();

    if (tid < 4) {
        int i = tid;
        const float* av = aV + i * 64;
        const float* bvv = sv[2 + (i & 1)];
        float dot = 0.f, na = 0.f, nb = 0.f;
        #pragma unroll
        for (int h = 0; h < 64; h++) {
            dot += av[h] * bvv[h];
            na  += av[h] * av[h];
            nb  += bvv[h] * bvv[h];
        }
        na = fmaxf(sqrtf(na), 1e-8f);
        nb = fmaxf(sqrtf(nb), 1e-8f);
        feat[256 + i] = dot / (na * nb);
    }
    feat[260 + tid] = sv[tid >> 6][tid & 63];
    __syncthreads();

    {
        int j = tid >> 2, part = tid & 3;
        const float* wrow = fc0_w + (size_t)j * 516 + part * 129;
        const float* fr = feat + part * 129;
        float s = 0.f;
        #pragma unroll 4
        for (int i = 0; i < 129; i++) s += fr[i] * wrow[i];
        s += __shfl_xor_sync(0xffffffff, s, 1);
        s += __shfl_xor_sync(0xffffffff, s, 2);
        if (part == 0) h1[j] = gelu_f(fc0_b[j] + s);
    }
    __syncthreads();

    if (tid == 0) {
        float l0 = fc1_b[0], l1 = fc1_b[1];
        #pragma unroll
        for (int j = 0; j < 64; j++) { l0 += h1[j] * fc1_w[j]; l1 += h1[j] * fc1_w[64 + j]; }
        l0 = gelu_f(l0); l1 = gelu_f(l1);
        float m = fmaxf(l0, l1);
        float ea = expf(l0 - m), eb = expf(l1 - m);
        float inv = 1.f / (ea + eb);
        out[b * 2 + 0] = ea * inv;
        out[b * 2 + 1] = eb * inv;
    }
}

// =====================================================================
typedef CUresult (*EncodeTiledFn)(
    CUtensorMap*, CUtensorMapDataType, cuuint32_t, void*,
    const cuuint64_t*, const cuuint64_t*, const cuuint32_t*, const cuuint32_t*,
    CUtensorMapInterleave, CUtensorMapSwizzle, CUtensorMapL2promotion,
    CUtensorMapFloatOOBfill);

extern "C" void kernel_launch(void* const* d_in, const int* in_sizes, int n_in,
                              void* d_out, int out_size)
{
    const float* token   = (const float*)d_in[0];
    const int*   kw_idx  = (const int*)  d_in[1];
    const float* q_w     = (const float*)d_in[2];
    const float* q_b     = (const float*)d_in[3];
    const float* k_w     = (const float*)d_in[4];
    const float* k_b     = (const float*)d_in[5];
    const float* v_w     = (const float*)d_in[6];
    const float* v_b     = (const float*)d_in[7];
    const float* mi_w    = (const float*)d_in[8];
    const float* mi_b    = (const float*)d_in[9];
    const float* inter_w = (const float*)d_in[10];
    const float* inter_b = (const float*)d_in[11];
    const float* fc0_w   = (const float*)d_in[12];
    const float* fc0_b   = (const float*)d_in[13];
    const float* fc1_w   = (const float*)d_in[14];
    const float* fc1_b   = (const float*)d_in[15];
    float* out = (float*)d_out;

    void* encPtr = nullptr;
    cudaDriverEntryPointQueryResult qr;
    cudaGetDriverEntryPointByVersion("cuTensorMapEncodeTiled", &encPtr, 12000,
                                     cudaEnableDefault, &qr);
    EncodeTiledFn enc = (EncodeTiledFn)encPtr;

    void* wAddr = nullptr;
    cudaGetSymbolAddress(&wAddr, g_Wb);

    CUtensorMap tmW;
    {
        cuuint64_t dims[2]    = {D_, 192};
        cuuint64_t strides[1] = {D_ * 2};
        cuuint32_t box[2]     = {64, 64};
        cuuint32_t es[2]      = {1, 1};
        enc(&tmW, CU_TENSOR_MAP_DATA_TYPE_BFLOAT16, 2, wAddr,
            dims, strides, box, es,
            CU_TENSOR_MAP_INTERLEAVE_NONE, CU_TENSOR_MAP_SWIZZLE_128B,
            CU_TENSOR_MAP_L2_PROMOTION_L2_128B, CU_TENSOR_MAP_FLOAT_OOB_FILL_NONE);
    }

    cudaFuncSetAttribute(fused_kernel,
                         cudaFuncAttributeMaxDynamicSharedMemorySize, GEMM_SMEM);

    wpack_kernel<<<24, 512>>>(q_w, k_w, v_w);
    fused_kernel<<<384, 128, GEMM_SMEM>>>(tmW, token, kw_idx);
    head_kernel<<<B_, 256>>>(q_b, k_b, v_b, mi_w, mi_b, inter_w, inter_b,
                             fc0_w, fc0_b, fc1_w, fc1_b, out);
}

// round 10
// speedup vs baseline: 1.9412x; 1.9412x over previous
#include <cuda_runtime.h>
#include <cuda.h>
#include <cuda_bf16.h>
#include <math.h>
#include <stdint.h>

// Problem constants
#define B_   128
#define S_   256
#define D_   1024
#define DH_  64
#define K_   8
#define L_   2
#define NROWS 18          // 16 gathered rows + vmax + vavg
#define MTOT (B_*2*NROWS) // 4608
#define NTOT 256          // q(64)|k(64)|v(64)|mi(64)

// -------- scratch (no allocations allowed) --------
__device__ uint16_t g_Xb[(size_t)MTOT * D_];   // gathered rows + pooled, bf16
__device__ uint16_t g_Wb[(size_t)NTOT * D_];   // packed weights q|k|v|mi, bf16
__device__ float    g_Y [(size_t)MTOT * NTOT]; // projection outputs (f32)

__device__ __forceinline__ uint2 f4_to_bf4(float4 v) {
    __nv_bfloat162 lo = __floats2bfloat162_rn(v.x, v.y);
    __nv_bfloat162 hi = __floats2bfloat162_rn(v.z, v.w);
    uint2 r;
    r.x = *reinterpret_cast<uint32_t*>(&lo);
    r.y = *reinterpret_cast<uint32_t*>(&hi);
    return r;
}

__device__ __forceinline__ void mbar_wait(uint32_t mbar, int phase) {
    asm volatile(
        "{\n\t.reg .pred P;\n"
        "W%=:\n\t"
        "mbarrier.try_wait.parity.acquire.cta.shared::cta.b64 P, [%0], %1, 0x989680;\n\t"
        "@P bra D%=;\n\t"
        "bra W%=;\n"
        "D%=:\n\t}"
        :: "r"(mbar), "r"(phase) : "memory");
}

// =====================================================================
// Kernel 1: gather via cp.async.bulk row copies (blocks 0..255, 512 thr)
//           + weight pack (blocks 256..287)
// =====================================================================
#define GATH_SMEM 65536   // 16 rows x 4KB f32 staging

__global__ void __launch_bounds__(512)
gather_pack_kernel(const float* __restrict__ token,
                   const int* __restrict__ kw_idx,
                   const float* __restrict__ wq, const float* __restrict__ wk,
                   const float* __restrict__ wv, const float* __restrict__ wmi)
{
    int tid = threadIdx.x;
    if (blockIdx.x >= 256) {
        int f4base = (blockIdx.x - 256) * 2048 + tid;
        #pragma unroll
        for (int i = 0; i < 4; i++) {
            int f4 = f4base + i * 512;        // 0..65535
            int wsel = f4 >> 14;              // 16384 float4 per matrix
            const float* W = (wsel == 0) ? wq : (wsel == 1) ? wk :
                             (wsel == 2) ? wv : wmi;
            float4 v = reinterpret_cast<const float4*>(W)[f4 & 16383];
            reinterpret_cast<uint2*>(g_Wb)[f4] = f4_to_bf4(v);
        }
        return;
    }

    extern __shared__ __align__(16) float smemf[];   // 16 rows x 1024 f32
    __shared__ __align__(8) uint64_t mbar1;
    __shared__ int idx[K_];
    __shared__ float4 pmax[2][256];
    __shared__ float4 psum[2][256];

    const uint32_t mb = (uint32_t)__cvta_generic_to_shared(&mbar1);
    const uint32_t smem_s = (uint32_t)__cvta_generic_to_shared(smemf);

    int bs = blockIdx.x;
    int b = bs >> 1, s = bs & 1;
    if (tid < K_)
        idx[tid] = kw_idx[(b * 2 + (1 - s)) * K_ + tid];
    if (tid == 0)
        asm volatile("mbarrier.init.shared.b64 [%0], %1;" :: "r"(mb), "r"(1) : "memory");
    __syncthreads();

    if (tid == 0) {
        asm volatile("mbarrier.arrive.expect_tx.shared.b64 _, [%0], %1;"
                     :: "r"(mb), "r"(GATH_SMEM) : "memory");
        const float* tbase = token + (((size_t)b * 2 + s) * L_) * S_ * D_;
        #pragma unroll
        for (int r = 0; r < 16; r++) {
            int l = r >> 3, k = r & 7;
            const float* src = tbase + ((size_t)l * S_ + idx[k]) * D_;
            asm volatile(
                "cp.async.bulk.shared::cta.global.mbarrier::complete_tx::bytes "
                "[%0], [%1], %2, [%3];"
                :: "r"(smem_s + r * 4096), "l"(src), "r"(4096), "r"(mb) : "memory");
        }
    }
    mbar_wait(mb, 0);

    int col = tid & 255;   // float4 column
    int rp  = tid >> 8;    // row half 0..1
    uint16_t* Xrow = g_Xb + (size_t)bs * NROWS * D_;
    const float4* sf4 = reinterpret_cast<const float4*>(smemf);

    float4 mx = make_float4(-3.4e38f, -3.4e38f, -3.4e38f, -3.4e38f);
    float4 sm = make_float4(0.f, 0.f, 0.f, 0.f);

    #pragma unroll
    for (int j = 0; j < 8; j++) {
        int r = rp * 8 + j;
        float4 v = sf4[r * 256 + col];
        reinterpret_cast<uint2*>(Xrow + (size_t)r * D_)[col] = f4_to_bf4(v);
        mx.x = fmaxf(mx.x, v.x); mx.y = fmaxf(mx.y, v.y);
        mx.z = fmaxf(mx.z, v.z); mx.w = fmaxf(mx.w, v.w);
        sm.x += v.x; sm.y += v.y; sm.z += v.z; sm.w += v.w;
    }
    pmax[rp][col] = mx;
    psum[rp][col] = sm;
    __syncthreads();

    if (tid < 256) {
        float4 m0 = pmax[0][col], m1 = pmax[1][col];
        float4 s0 = psum[0][col], s1 = psum[1][col];
        float4 M, S;
        M.x = fmaxf(m0.x, m1.x); M.y = fmaxf(m0.y, m1.y);
        M.z = fmaxf(m0.z, m1.z); M.w = fmaxf(m0.w, m1.w);
        S.x = (s0.x + s1.x) * (1.f/16.f);
        S.y = (s0.y + s1.y) * (1.f/16.f);
        S.z = (s0.z + s1.z) * (1.f/16.f);
        S.w = (s0.w + s1.w) * (1.f/16.f);
        reinterpret_cast<uint2*>(Xrow + (size_t)16 * D_)[col] = f4_to_bf4(M);
        reinterpret_cast<uint2*>(Xrow + (size_t)17 * D_)[col] = f4_to_bf4(S);
    }
}

// =====================================================================
// Kernel 2: bf16 tensor GEMM  g_Y[M,256] = X @ W^T   (R6 baseline)
// 64x128x64 block tiles, warp tile 32x32, TMA (SW128) + mbarrier
// 3-stage ring, ldmatrix.x4, mma.m16n8k16.bf16. grid (72, 2).
// =====================================================================
#define A_BYTES (64 * 128)               // 8192 B per stage
#define B_BYTES (128 * 128)              // 16384 B per stage
#define STAGE_BYTES (A_BYTES + B_BYTES)  // 24576
#define GEMM_SMEM (3 * STAGE_BYTES)      // 73728

__device__ __forceinline__ void tma_2d(uint32_t dst, const CUtensorMap* tm,
                                       int x, int y, uint32_t mbar) {
    asm volatile(
        "cp.async.bulk.tensor.2d.shared::cta.global.tile.mbarrier::complete_tx::bytes "
        "[%0], [%1, {%2, %3}], [%4];"
        :: "r"(dst), "l"(tm), "r"(x), "r"(y), "r"(mbar) : "memory");
}

__global__ void __launch_bounds__(256, 1)
gemm_tc_kernel(const __grid_constant__ CUtensorMap tmA,
               const __grid_constant__ CUtensorMap tmB)
{
    extern __shared__ __align__(1024) uint16_t smem_b[];
    __shared__ __align__(8) uint64_t mbar_s[6];   // full[0..2], empty[0..2]

    const uint32_t smem_s = (uint32_t)__cvta_generic_to_shared(smem_b);
    const uint32_t mb     = (uint32_t)__cvta_generic_to_shared(mbar_s);

    const int tid  = threadIdx.x;
    const int lane = tid & 31;
    const int warp = tid >> 5;
    const int wm   = warp >> 2;
    const int wn   = warp & 3;
    const int m0   = blockIdx.x * 64;
    const int n0   = blockIdx.y * 128;

    if (tid == 0) {
        #pragma unroll
        for (int s = 0; s < 3; s++) {
            asm volatile("mbarrier.init.shared.b64 [%0], %1;" :: "r"(mb + s * 8), "r"(1) : "memory");
            asm volatile("mbarrier.init.shared.b64 [%0], %1;" :: "r"(mb + 24 + s * 8), "r"(256) : "memory");
        }
    }
    __syncthreads();

    if (tid == 0) {
        #pragma unroll
        for (int s = 0; s < 3; s++) {
            uint32_t fb = mb + s * 8;
            asm volatile("mbarrier.arrive.expect_tx.shared.b64 _, [%0], %1;"
                         :: "r"(fb), "r"(STAGE_BYTES) : "memory");
            uint32_t base = smem_s + s * STAGE_BYTES;
            tma_2d(base,           &tmA, s * 64, m0, fb);
            tma_2d(base + A_BYTES, &tmB, s * 64, n0, fb);
        }
    }

    float c[2][4][4];
    #pragma unroll
    for (int i = 0; i < 2; i++)
        #pragma unroll
        for (int j = 0; j < 4; j++)
            #pragma unroll
            for (int r = 0; r < 4; r++) c[i][j][r] = 0.f;

    const int j4   = lane >> 3;
    const int lr   = lane & 7;
    const int aRow = wm * 32 + (j4 & 1) * 8 + lr;
    const int aKj  = j4 >> 1;
    const int aSw  = aRow & 7;
    const int bRow = wn * 32 + (j4 >> 1) * 8 + lr;
    const int bKj  = j4 & 1;
    const int bSw  = bRow & 7;
    const uint32_t aByte0 = aRow * 128;
    const uint32_t aByte1 = (aRow + 16) * 128;
    const uint32_t bByte0 = bRow * 128;
    const uint32_t bByte1 = (bRow + 16) * 128;

    int cs = 0, cph = 0;
    int ps = 0, pep = 0;

    for (int kt = 0; kt < 16; kt++) {
        mbar_wait(mb + cs * 8, cph);

        const uint32_t As = smem_s + cs * STAGE_BYTES;
        const uint32_t Bs = As + A_BYTES;

        #pragma unroll
        for (int step = 0; step < 4; step++) {
            const int cA = (2 * step + aKj) ^ aSw;
            const int cB = (2 * step + bKj) ^ bSw;
            uint32_t a0[4], a1[4], b0[4], b1[4];
            {
                uint32_t addr = As + aByte0 + (cA << 4);
                asm volatile("ldmatrix.sync.aligned.m8n8.x4.shared.b16 {%0,%1,%2,%3}, [%4];"
                             : "=r"(a0[0]), "=r"(a0[1]), "=r"(a0[2]), "=r"(a0[3]) : "r"(addr));
            }
            {
                uint32_t addr = As + aByte1 + (cA << 4);
                asm volatile("ldmatrix.sync.aligned.m8n8.x4.shared.b16 {%0,%1,%2,%3}, [%4];"
                             : "=r"(a1[0]), "=r"(a1[1]), "=r"(a1[2]), "=r"(a1[3]) : "r"(addr));
            }
            {
                uint32_t addr = Bs + bByte0 + (cB << 4);
                asm volatile("ldmatrix.sync.aligned.m8n8.x4.shared.b16 {%0,%1,%2,%3}, [%4];"
                             : "=r"(b0[0]), "=r"(b0[1]), "=r"(b0[2]), "=r"(b0[3]) : "r"(addr));
            }
            {
                uint32_t addr = Bs + bByte1 + (cB << 4);
                asm volatile("ldmatrix.sync.aligned.m8n8.x4.shared.b16 {%0,%1,%2,%3}, [%4];"
                             : "=r"(b1[0]), "=r"(b1[1]), "=r"(b1[2]), "=r"(b1[3]) : "r"(addr));
            }
            #pragma unroll
            for (int mt = 0; mt < 2; mt++) {
                const uint32_t* a = mt ? a1 : a0;
                #pragma unroll
                for (int nt = 0; nt < 4; nt++) {
                    const uint32_t* bb = (nt < 2) ? &b0[(nt & 1) * 2] : &b1[(nt & 1) * 2];
                    asm volatile(
                        "mma.sync.aligned.m16n8k16.row.col.f32.bf16.bf16.f32 "
                        "{%0,%1,%2,%3}, {%4,%5,%6,%7}, {%8,%9}, {%0,%1,%2,%3};"
                        : "+f"(c[mt][nt][0]), "+f"(c[mt][nt][1]),
                          "+f"(c[mt][nt][2]), "+f"(c[mt][nt][3])
                        : "r"(a[0]), "r"(a[1]), "r"(a[2]), "r"(a[3]),
                          "r"(bb[0]), "r"(bb[1]));
                }
            }
        }

        asm volatile("mbarrier.arrive.shared.b64 _, [%0];" :: "r"(mb + 24 + cs * 8) : "memory");

        if (tid == 0 && kt + 3 < 16) {
            mbar_wait(mb + 24 + ps * 8, pep);
            uint32_t fb = mb + ps * 8;
            asm volatile("mbarrier.arrive.expect_tx.shared.b64 _, [%0], %1;"
                         :: "r"(fb), "r"(STAGE_BYTES) : "memory");
            uint32_t base = smem_s + ps * STAGE_BYTES;
            tma_2d(base,           &tmA, (kt + 3) * 64, m0, fb);
            tma_2d(base + A_BYTES, &tmB, (kt + 3) * 64, n0, fb);
            ps++; if (ps == 3) { ps = 0; pep ^= 1; }
        }

        cs++; if (cs == 3) { cs = 0; cph ^= 1; }
    }

    const int g  = lane >> 2;
    const int tg = lane & 3;
    #pragma unroll
    for (int mt = 0; mt < 2; mt++) {
        const int rA = m0 + wm * 32 + mt * 16 + g;
        #pragma unroll
        for (int nt = 0; nt < 4; nt++) {
            const int col = n0 + wn * 32 + nt * 8 + 2 * tg;
            *reinterpret_cast<float2*>(g_Y + (size_t)rA * NTOT + col) =
                make_float2(c[mt][nt][0], c[mt][nt][1]);
            *reinterpret_cast<float2*>(g_Y + (size_t)(rA + 8) * NTOT + col) =
                make_float2(c[mt][nt][2], c[mt][nt][3]);
        }
    }
}

// =====================================================================
// Kernel 3: per-b heads. grid = B blocks, 256 threads.  (R6 baseline)
// =====================================================================
__device__ __forceinline__ float gelu_f(float x) {
    return 0.5f * x * (1.0f + erff(x * 0.70710678118654752440f));
}

__global__ void __launch_bounds__(256)
head_kernel(const float* __restrict__ q_b, const float* __restrict__ k_b,
            const float* __restrict__ v_b, const float* __restrict__ mi_b,
            const float* __restrict__ inter_w, const float* __restrict__ inter_b,
            const float* __restrict__ fc0_w, const float* __restrict__ fc0_b,
            const float* __restrict__ fc1_w, const float* __restrict__ fc1_b,
            float* __restrict__ out)
{
    __shared__ float q0[1024], k0[1024], v0[1024];
    __shared__ float q1[1024], k1[1024], v1[1024];
    __shared__ float att[512];
    __shared__ float e1s[1024], e2s[1024];
    __shared__ float sv[4][64];
    __shared__ float aV[256];
    __shared__ float feat[516];
    __shared__ float h1[64];

    int b = blockIdx.x;
    int tid = threadIdx.x;
    const float* Y0 = g_Y + (size_t)(b * 2 + 0) * NROWS * NTOT;
    const float* Y1 = g_Y + (size_t)(b * 2 + 1) * NROWS * NTOT;

    for (int t = tid; t < 1024; t += 256) {
        int n = t >> 6, h = t & 63;
        q0[t] = Y0[n * NTOT +       h] + q_b[h];
        k0[t] = Y0[n * NTOT +  64 + h] + k_b[h];
        v0[t] = Y0[n * NTOT + 128 + h] + v_b[h];
        q1[t] = Y1[n * NTOT +       h] + q_b[h];
        k1[t] = Y1[n * NTOT +  64 + h] + k_b[h];
        v1[t] = Y1[n * NTOT + 128 + h] + v_b[h];
    }
    if (tid < 64) {
        int h = tid;
        sv[0][h] = Y0[16 * NTOT + 192 + h] + mi_b[h];
        sv[1][h] = Y0[17 * NTOT + 192 + h] + mi_b[h];
        sv[2][h] = Y1[16 * NTOT + 192 + h] + mi_b[h];
        sv[3][h] = Y1[17 * NTOT + 192 + h] + mi_b[h];
    }
    __syncthreads();

    for (int e = tid; e < 512; e += 256) {
        int which = e >> 8, n = (e >> 4) & 15, m = e & 15;
        const float* qq = which ? q1 : q0;
        const float* kk = which ? k0 : k1;
        float s = 0.f;
        #pragma unroll
        for (int h = 0; h < 64; h++) s += qq[n * 64 + h] * kk[m * 64 + h];
        att[e] = s * 0.125f;
    }
    __syncthreads();

    for (int e = tid; e < 2048; e += 256) {
        int which = e >> 10, n = (e >> 6) & 15, h = e & 63;
        const float* vv = which ? v0 : v1;
        float s = 0.f;
        #pragma unroll
        for (int m = 0; m < 16; m++) s += att[which * 256 + n * 16 + m] * vv[m * 64 + h];
        (which ? e2s : e1s)[n * 64 + h] = s;
    }
    __syncthreads();

    if (tid < 128) {
        int which = tid >> 6, hh = tid & 63;
        const float* E = which ? e2s : e1s;
        float mx = -3.4e38f, sm = 0.f;
        #pragma unroll
        for (int n = 0; n < 16; n++) { float v = E[n * 64 + hh]; mx = fmaxf(mx, v); sm += v; }
        feat[which * 128 + hh]      = mx;
        feat[which * 128 + 64 + hh] = sm * (1.f / 16.f);
    }

    {
        int i = tid >> 6, j = tid & 63;
        const float* src = sv[i >> 1];
        float s = inter_b[i * 64 + j];
        const float* wrow = inter_w + ((size_t)i * 64 + j) * 64;
        #pragma unroll
        for (int h = 0; h < 64; h++) s += wrow[h] * src[h];
        aV[i * 64 + j] = s;
    }
    __syncthreads();

    if (tid < 4) {
        int i = tid;
        const float* av = aV + i * 64;
        const float* bvv = sv[2 + (i & 1)];
        float dot = 0.f, na = 0.f, nb = 0.f;
        #pragma unroll
        for (int h = 0; h < 64; h++) {
            dot += av[h] * bvv[h];
            na  += av[h] * av[h];
            nb  += bvv[h] * bvv[h];
        }
        na = fmaxf(sqrtf(na), 1e-8f);
        nb = fmaxf(sqrtf(nb), 1e-8f);
        feat[256 + i] = dot / (na * nb);
    }
    feat[260 + tid] = sv[tid >> 6][tid & 63];
    __syncthreads();

    {
        int j = tid >> 2, part = tid & 3;
        const float* wrow = fc0_w + (size_t)j * 516 + part * 129;
        const float* fr = feat + part * 129;
        float s = 0.f;
        #pragma unroll 4
        for (int i = 0; i < 129; i++) s += fr[i] * wrow[i];
        s += __shfl_xor_sync(0xffffffff, s, 1);
        s += __shfl_xor_sync(0xffffffff, s, 2);
        if (part == 0) h1[j] = gelu_f(fc0_b[j] + s);
    }
    __syncthreads();

    if (tid == 0) {
        float l0 = fc1_b[0], l1 = fc1_b[1];
        #pragma unroll
        for (int j = 0; j < 64; j++) { l0 += h1[j] * fc1_w[j]; l1 += h1[j] * fc1_w[64 + j]; }
        l0 = gelu_f(l0); l1 = gelu_f(l1);
        float m = fmaxf(l0, l1);
        float ea = expf(l0 - m), eb = expf(l1 - m);
        float inv = 1.f / (ea + eb);
        out[b * 2 + 0] = ea * inv;
        out[b * 2 + 1] = eb * inv;
    }
}

// =====================================================================
typedef CUresult (*EncodeTiledFn)(
    CUtensorMap*, CUtensorMapDataType, cuuint32_t, void*,
    const cuuint64_t*, const cuuint64_t*, const cuuint32_t*, const cuuint32_t*,
    CUtensorMapInterleave, CUtensorMapSwizzle, CUtensorMapL2promotion,
    CUtensorMapFloatOOBfill);

extern "C" void kernel_launch(void* const* d_in, const int* in_sizes, int n_in,
                              void* d_out, int out_size)
{
    const float* token   = (const float*)d_in[0];
    const int*   kw_idx  = (const int*)  d_in[1];
    const float* q_w     = (const float*)d_in[2];
    const float* q_b     = (const float*)d_in[3];
    const float* k_w     = (const float*)d_in[4];
    const float* k_b     = (const float*)d_in[5];
    const float* v_w     = (const float*)d_in[6];
    const float* v_b     = (const float*)d_in[7];
    const float* mi_w    = (const float*)d_in[8];
    const float* mi_b    = (const float*)d_in[9];
    const float* inter_w = (const float*)d_in[10];
    const float* inter_b = (const float*)d_in[11];
    const float* fc0_w   = (const float*)d_in[12];
    const float* fc0_b   = (const float*)d_in[13];
    const float* fc1_w   = (const float*)d_in[14];
    const float* fc1_b   = (const float*)d_in[15];
    float* out = (float*)d_out;

    void* encPtr = nullptr;
    cudaDriverEntryPointQueryResult qr;
    cudaGetDriverEntryPointByVersion("cuTensorMapEncodeTiled", &encPtr, 12000,
                                     cudaEnableDefault, &qr);
    EncodeTiledFn enc = (EncodeTiledFn)encPtr;

    void* xAddr = nullptr;
    void* wAddr = nullptr;
    cudaGetSymbolAddress(&xAddr, g_Xb);
    cudaGetSymbolAddress(&wAddr, g_Wb);

    CUtensorMap tmA, tmB;
    {
        cuuint64_t dims[2]    = {D_, MTOT};
        cuuint64_t strides[1] = {D_ * 2};
        cuuint32_t box[2]     = {64, 64};
        cuuint32_t es[2]      = {1, 1};
        enc(&tmA, CU_TENSOR_MAP_DATA_TYPE_BFLOAT16, 2, xAddr,
            dims, strides, box, es,
            CU_TENSOR_MAP_INTERLEAVE_NONE, CU_TENSOR_MAP_SWIZZLE_128B,
            CU_TENSOR_MAP_L2_PROMOTION_L2_128B, CU_TENSOR_MAP_FLOAT_OOB_FILL_NONE);
    }
    {
        cuuint64_t dims[2]    = {D_, NTOT};
        cuuint64_t strides[1] = {D_ * 2};
        cuuint32_t box[2]     = {64, 128};
        cuuint32_t es[2]      = {1, 1};
        enc(&tmB, CU_TENSOR_MAP_DATA_TYPE_BFLOAT16, 2, wAddr,
            dims, strides, box, es,
            CU_TENSOR_MAP_INTERLEAVE_NONE, CU_TENSOR_MAP_SWIZZLE_128B,
            CU_TENSOR_MAP_L2_PROMOTION_L2_128B, CU_TENSOR_MAP_FLOAT_OOB_FILL_NONE);
    }

    cudaFuncSetAttribute(gather_pack_kernel,
                         cudaFuncAttributeMaxDynamicSharedMemorySize, GATH_SMEM);
    cudaFuncSetAttribute(gemm_tc_kernel,
                         cudaFuncAttributeMaxDynamicSharedMemorySize, GEMM_SMEM);

    gather_pack_kernel<<<256 + 32, 512, GATH_SMEM>>>(token, kw_idx, q_w, k_w, v_w, mi_w);
    gemm_tc_kernel<<<dim3(MTOT / 64, 2), 256, GEMM_SMEM>>>(tmA, tmB);
    head_kernel<<<B_, 256>>>(q_b, k_b, v_b, mi_b, inter_w, inter_b,
                             fc0_w, fc0_b, fc1_w, fc1_b, out);
}

// round 11
// speedup vs baseline: 2.7049x; 1.3934x over previous
#include <cuda_runtime.h>
#include <cuda.h>
#include <cuda_bf16.h>
#include <math.h>
#include <stdint.h>

// Problem constants
#define B_   128
#define S_   256
#define D_   1024
#define DH_  64
#define K_   8
#define L_   2
#define NROWS 18          // 16 gathered rows + vmax + vavg
#define MTOT (B_*2*NROWS) // 4608
#define NTOT 256          // q(64)|k(64)|v(64)|mi(64)

// -------- scratch (no allocations allowed) --------
__device__ uint16_t g_Xb[(size_t)MTOT * D_];   // gathered rows + pooled, bf16
__device__ uint16_t g_Wb[(size_t)NTOT * D_];   // packed weights q|k|v|mi, bf16
__device__ float    g_Y [(size_t)MTOT * NTOT]; // projection outputs (f32)

__device__ __forceinline__ uint2 f4_to_bf4(float4 v) {
    __nv_bfloat162 lo = __floats2bfloat162_rn(v.x, v.y);
    __nv_bfloat162 hi = __floats2bfloat162_rn(v.z, v.w);
    uint2 r;
    r.x = *reinterpret_cast<uint32_t*>(&lo);
    r.y = *reinterpret_cast<uint32_t*>(&hi);
    return r;
}

// =====================================================================
// Kernel 1: gather (blocks 0..255, 512 thr: 2 row-halves x 256 cols)
//           + weight pack (blocks 256..287, 512 thr)     [R6 version]
// =====================================================================
__global__ void __launch_bounds__(512)
gather_pack_kernel(const float* __restrict__ token,
                   const int* __restrict__ kw_idx,
                   const float* __restrict__ wq, const float* __restrict__ wk,
                   const float* __restrict__ wv, const float* __restrict__ wmi)
{
    int tid = threadIdx.x;
    if (blockIdx.x >= 256) {
        int f4base = (blockIdx.x - 256) * 2048 + tid;
        #pragma unroll
        for (int i = 0; i < 4; i++) {
            int f4 = f4base + i * 512;
            int wsel = f4 >> 14;
            const float* W = (wsel == 0) ? wq : (wsel == 1) ? wk :
                             (wsel == 2) ? wv : wmi;
            float4 v = reinterpret_cast<const float4*>(W)[f4 & 16383];
            reinterpret_cast<uint2*>(g_Wb)[f4] = f4_to_bf4(v);
        }
        return;
    }

    __shared__ int idx[K_];
    __shared__ float4 pmax[2][256];
    __shared__ float4 psum[2][256];

    int bs = blockIdx.x;
    int b = bs >> 1, s = bs & 1;
    if (tid < K_)
        idx[tid] = kw_idx[(b * 2 + (1 - s)) * K_ + tid];
    __syncthreads();

    int col = tid & 255;
    int rp  = tid >> 8;
    const float* tbase = token + (((size_t)b * 2 + s) * L_) * S_ * D_;
    uint16_t* Xrow = g_Xb + (size_t)bs * NROWS * D_;

    float4 mx = make_float4(-3.4e38f, -3.4e38f, -3.4e38f, -3.4e38f);
    float4 sm = make_float4(0.f, 0.f, 0.f, 0.f);

    #pragma unroll
    for (int j = 0; j < 8; j++) {
        int r = rp * 8 + j;
        float4 v = reinterpret_cast<const float4*>(
            tbase + ((size_t)rp * S_ + idx[j]) * D_)[col];
        reinterpret_cast<uint2*>(Xrow + (size_t)r * D_)[col] = f4_to_bf4(v);
        mx.x = fmaxf(mx.x, v.x); mx.y = fmaxf(mx.y, v.y);
        mx.z = fmaxf(mx.z, v.z); mx.w = fmaxf(mx.w, v.w);
        sm.x += v.x; sm.y += v.y; sm.z += v.z; sm.w += v.w;
    }
    pmax[rp][col] = mx;
    psum[rp][col] = sm;
    __syncthreads();

    if (tid < 256) {
        float4 m0 = pmax[0][col], m1 = pmax[1][col];
        float4 s0 = psum[0][col], s1 = psum[1][col];
        float4 M, S;
        M.x = fmaxf(m0.x, m1.x); M.y = fmaxf(m0.y, m1.y);
        M.z = fmaxf(m0.z, m1.z); M.w = fmaxf(m0.w, m1.w);
        S.x = (s0.x + s1.x) * (1.f/16.f);
        S.y = (s0.y + s1.y) * (1.f/16.f);
        S.z = (s0.z + s1.z) * (1.f/16.f);
        S.w = (s0.w + s1.w) * (1.f/16.f);
        reinterpret_cast<uint2*>(Xrow + (size_t)16 * D_)[col] = f4_to_bf4(M);
        reinterpret_cast<uint2*>(Xrow + (size_t)17 * D_)[col] = f4_to_bf4(S);
    }
}

// =====================================================================
// Kernel 2: bf16 tensor GEMM  g_Y[M,256] = X @ W^T   (R6 baseline)
// =====================================================================
#define A_BYTES (64 * 128)
#define B_BYTES (128 * 128)
#define STAGE_BYTES (A_BYTES + B_BYTES)
#define GEMM_SMEM (3 * STAGE_BYTES)

__device__ __forceinline__ void mbar_wait(uint32_t mbar, int phase) {
    asm volatile(
        "{\n\t.reg .pred P;\n"
        "W%=:\n\t"
        "mbarrier.try_wait.parity.acquire.cta.shared::cta.b64 P, [%0], %1, 0x989680;\n\t"
        "@P bra D%=;\n\t"
        "bra W%=;\n"
        "D%=:\n\t}"
        :: "r"(mbar), "r"(phase) : "memory");
}

__device__ __forceinline__ void tma_2d(uint32_t dst, const CUtensorMap* tm,
                                       int x, int y, uint32_t mbar) {
    asm volatile(
        "cp.async.bulk.tensor.2d.shared::cta.global.tile.mbarrier::complete_tx::bytes "
        "[%0], [%1, {%2, %3}], [%4];"
        :: "r"(dst), "l"(tm), "r"(x), "r"(y), "r"(mbar) : "memory");
}

__global__ void __launch_bounds__(256, 1)
gemm_tc_kernel(const __grid_constant__ CUtensorMap tmA,
               const __grid_constant__ CUtensorMap tmB)
{
    extern __shared__ __align__(1024) uint16_t smem_b[];
    __shared__ __align__(8) uint64_t mbar_s[6];

    const uint32_t smem_s = (uint32_t)__cvta_generic_to_shared(smem_b);
    const uint32_t mb     = (uint32_t)__cvta_generic_to_shared(mbar_s);

    const int tid  = threadIdx.x;
    const int lane = tid & 31;
    const int warp = tid >> 5;
    const int wm   = warp >> 2;
    const int wn   = warp & 3;
    const int m0   = blockIdx.x * 64;
    const int n0   = blockIdx.y * 128;

    if (tid == 0) {
        #pragma unroll
        for (int s = 0; s < 3; s++) {
            asm volatile("mbarrier.init.shared.b64 [%0], %1;" :: "r"(mb + s * 8), "r"(1) : "memory");
            asm volatile("mbarrier.init.shared.b64 [%0], %1;" :: "r"(mb + 24 + s * 8), "r"(256) : "memory");
        }
    }
    __syncthreads();

    if (tid == 0) {
        #pragma unroll
        for (int s = 0; s < 3; s++) {
            uint32_t fb = mb + s * 8;
            asm volatile("mbarrier.arrive.expect_tx.shared.b64 _, [%0], %1;"
                         :: "r"(fb), "r"(STAGE_BYTES) : "memory");
            uint32_t base = smem_s + s * STAGE_BYTES;
            tma_2d(base,           &tmA, s * 64, m0, fb);
            tma_2d(base + A_BYTES, &tmB, s * 64, n0, fb);
        }
    }

    float c[2][4][4];
    #pragma unroll
    for (int i = 0; i < 2; i++)
        #pragma unroll
        for (int j = 0; j < 4; j++)
            #pragma unroll
            for (int r = 0; r < 4; r++) c[i][j][r] = 0.f;

    const int j4   = lane >> 3;
    const int lr   = lane & 7;
    const int aRow = wm * 32 + (j4 & 1) * 8 + lr;
    const int aKj  = j4 >> 1;
    const int aSw  = aRow & 7;
    const int bRow = wn * 32 + (j4 >> 1) * 8 + lr;
    const int bKj  = j4 & 1;
    const int bSw  = bRow & 7;
    const uint32_t aByte0 = aRow * 128;
    const uint32_t aByte1 = (aRow + 16) * 128;
    const uint32_t bByte0 = bRow * 128;
    const uint32_t bByte1 = (bRow + 16) * 128;

    int cs = 0, cph = 0;
    int ps = 0, pep = 0;

    for (int kt = 0; kt < 16; kt++) {
        mbar_wait(mb + cs * 8, cph);

        const uint32_t As = smem_s + cs * STAGE_BYTES;
        const uint32_t Bs = As + A_BYTES;

        #pragma unroll
        for (int step = 0; step < 4; step++) {
            const int cA = (2 * step + aKj) ^ aSw;
            const int cB = (2 * step + bKj) ^ bSw;
            uint32_t a0[4], a1[4], b0[4], b1[4];
            {
                uint32_t addr = As + aByte0 + (cA << 4);
                asm volatile("ldmatrix.sync.aligned.m8n8.x4.shared.b16 {%0,%1,%2,%3}, [%4];"
                             : "=r"(a0[0]), "=r"(a0[1]), "=r"(a0[2]), "=r"(a0[3]) : "r"(addr));
            }
            {
                uint32_t addr = As + aByte1 + (cA << 4);
                asm volatile("ldmatrix.sync.aligned.m8n8.x4.shared.b16 {%0,%1,%2,%3}, [%4];"
                             : "=r"(a1[0]), "=r"(a1[1]), "=r"(a1[2]), "=r"(a1[3]) : "r"(addr));
            }
            {
                uint32_t addr = Bs + bByte0 + (cB << 4);
                asm volatile("ldmatrix.sync.aligned.m8n8.x4.shared.b16 {%0,%1,%2,%3}, [%4];"
                             : "=r"(b0[0]), "=r"(b0[1]), "=r"(b0[2]), "=r"(b0[3]) : "r"(addr));
            }
            {
                uint32_t addr = Bs + bByte1 + (cB << 4);
                asm volatile("ldmatrix.sync.aligned.m8n8.x4.shared.b16 {%0,%1,%2,%3}, [%4];"
                             : "=r"(b1[0]), "=r"(b1[1]), "=r"(b1[2]), "=r"(b1[3]) : "r"(addr));
            }
            #pragma unroll
            for (int mt = 0; mt < 2; mt++) {
                const uint32_t* a = mt ? a1 : a0;
                #pragma unroll
                for (int nt = 0; nt < 4; nt++) {
                    const uint32_t* bb = (nt < 2) ? &b0[(nt & 1) * 2] : &b1[(nt & 1) * 2];
                    asm volatile(
                        "mma.sync.aligned.m16n8k16.row.col.f32.bf16.bf16.f32 "
                        "{%0,%1,%2,%3}, {%4,%5,%6,%7}, {%8,%9}, {%0,%1,%2,%3};"
                        : "+f"(c[mt][nt][0]), "+f"(c[mt][nt][1]),
                          "+f"(c[mt][nt][2]), "+f"(c[mt][nt][3])
                        : "r"(a[0]), "r"(a[1]), "r"(a[2]), "r"(a[3]),
                          "r"(bb[0]), "r"(bb[1]));
                }
            }
        }

        asm volatile("mbarrier.arrive.shared.b64 _, [%0];" :: "r"(mb + 24 + cs * 8) : "memory");

        if (tid == 0 && kt + 3 < 16) {
            mbar_wait(mb + 24 + ps * 8, pep);
            uint32_t fb = mb + ps * 8;
            asm volatile("mbarrier.arrive.expect_tx.shared.b64 _, [%0], %1;"
                         :: "r"(fb), "r"(STAGE_BYTES) : "memory");
            uint32_t base = smem_s + ps * STAGE_BYTES;
            tma_2d(base,           &tmA, (kt + 3) * 64, m0, fb);
            tma_2d(base + A_BYTES, &tmB, (kt + 3) * 64, n0, fb);
            ps++; if (ps == 3) { ps = 0; pep ^= 1; }
        }

        cs++; if (cs == 3) { cs = 0; cph ^= 1; }
    }

    const int g  = lane >> 2;
    const int tg = lane & 3;
    #pragma unroll
    for (int mt = 0; mt < 2; mt++) {
        const int rA = m0 + wm * 32 + mt * 16 + g;
        #pragma unroll
        for (int nt = 0; nt < 4; nt++) {
            const int col = n0 + wn * 32 + nt * 8 + 2 * tg;
            *reinterpret_cast<float2*>(g_Y + (size_t)rA * NTOT + col) =
                make_float2(c[mt][nt][0], c[mt][nt][1]);
            *reinterpret_cast<float2*>(g_Y + (size_t)(rA + 8) * NTOT + col) =
                make_float2(c[mt][nt][2], c[mt][nt][3]);
        }
    }
}

// =====================================================================
// Kernel 3: per-b heads — vectorized, conflict-free (padded stride 68)
// =====================================================================
__device__ __forceinline__ float gelu_f(float x) {
    return 0.5f * x * (1.0f + erff(x * 0.70710678118654752440f));
}
__device__ __forceinline__ float4 fma4(float4 a, float4 b, float4 c) {
    return make_float4(fmaf(a.x,b.x,c.x), fmaf(a.y,b.y,c.y),
                       fmaf(a.z,b.z,c.z), fmaf(a.w,b.w,c.w));
}
__device__ __forceinline__ float hsum4(float4 a) { return (a.x+a.y)+(a.z+a.w); }

#define PS 68   // padded row stride (floats)

__global__ void __launch_bounds__(256)
head_kernel(const float* __restrict__ q_b, const float* __restrict__ k_b,
            const float* __restrict__ v_b, const float* __restrict__ mi_b,
            const float* __restrict__ inter_w, const float* __restrict__ inter_b,
            const float* __restrict__ fc0_w, const float* __restrict__ fc0_b,
            const float* __restrict__ fc1_w, const float* __restrict__ fc1_b,
            float* __restrict__ out)
{
    __shared__ __align__(16) float q0[16*PS], k0[16*PS], v0[16*PS];
    __shared__ __align__(16) float q1[16*PS], k1[16*PS], v1[16*PS];
    __shared__ __align__(16) float e1s[16*PS], e2s[16*PS];
    __shared__ __align__(16) float att[512];
    __shared__ __align__(16) float sv[4][64];
    __shared__ __align__(16) float aV[4][64];
    __shared__ __align__(16) float feat[520];
    __shared__ float h1[64];

    int b = blockIdx.x;
    int tid = threadIdx.x;
    const float* Y0 = g_Y + (size_t)(b * 2 + 0) * NROWS * NTOT;
    const float* Y1 = g_Y + (size_t)(b * 2 + 1) * NROWS * NTOT;

    // Phase 1: load qkv (float4) + sv
    {
        int n = tid >> 4, c = tid & 15;
        float4 bq = reinterpret_cast<const float4*>(q_b)[c];
        float4 bk = reinterpret_cast<const float4*>(k_b)[c];
        float4 bv = reinterpret_cast<const float4*>(v_b)[c];
        const float4* r0 = reinterpret_cast<const float4*>(Y0 + n * NTOT);
        const float4* r1 = reinterpret_cast<const float4*>(Y1 + n * NTOT);
        float4 v;
        v = r0[c];      *reinterpret_cast<float4*>(&q0[n*PS + 4*c]) = fma4(v, make_float4(1,1,1,1), bq);
        v = r0[16 + c]; *reinterpret_cast<float4*>(&k0[n*PS + 4*c]) = fma4(v, make_float4(1,1,1,1), bk);
        v = r0[32 + c]; *reinterpret_cast<float4*>(&v0[n*PS + 4*c]) = fma4(v, make_float4(1,1,1,1), bv);
        v = r1[c];      *reinterpret_cast<float4*>(&q1[n*PS + 4*c]) = fma4(v, make_float4(1,1,1,1), bq);
        v = r1[16 + c]; *reinterpret_cast<float4*>(&k1[n*PS + 4*c]) = fma4(v, make_float4(1,1,1,1), bk);
        v = r1[32 + c]; *reinterpret_cast<float4*>(&v1[n*PS + 4*c]) = fma4(v, make_float4(1,1,1,1), bv);
    }
    {
        int i = tid >> 6, h = tid & 63;
        const float* Yx = (i < 2) ? Y0 : Y1;
        sv[i][h] = Yx[(16 + (i & 1)) * NTOT + 192 + h] + mi_b[h];
    }
    __syncthreads();

    // Phase 2: att (float4 dots) + inter projections
    #pragma unroll
    for (int e = tid; e < 512; e += 256) {
        int which = e >> 8, n = (e >> 4) & 15, m = e & 15;
        const float4* qq = reinterpret_cast<const float4*>((which ? q1 : q0) + n * PS);
        const float4* kk = reinterpret_cast<const float4*>((which ? k0 : k1) + m * PS);
        float4 acc = make_float4(0,0,0,0);
        #pragma unroll
        for (int t = 0; t < 16; t++) acc = fma4(qq[t], kk[t], acc);
        att[e] = hsum4(acc) * 0.125f;
    }
    {
        int i = tid >> 6, j = tid & 63;
        const float4* w = reinterpret_cast<const float4*>(inter_w + ((size_t)i * 64 + j) * 64);
        const float4* src = reinterpret_cast<const float4*>(sv[i >> 1]);
        float4 acc = make_float4(0,0,0,0);
        #pragma unroll
        for (int t = 0; t < 16; t++) acc = fma4(w[t], src[t], acc);
        aV[i][j] = inter_b[i * 64 + j] + hsum4(acc);
    }
    __syncthreads();

    // Phase 3: e = att @ v (h-vectorized) + cosines
    #pragma unroll
    for (int f = tid; f < 512; f += 256) {
        int which = f >> 8, n = (f >> 4) & 15, h4 = f & 15;
        const float* vv = which ? v0 : v1;
        const float* am = att + which * 256 + n * 16;
        float4 s = make_float4(0,0,0,0);
        #pragma unroll
        for (int m = 0; m < 16; m++) {
            float a = am[m];
            float4 vm = *reinterpret_cast<const float4*>(vv + m * PS + 4 * h4);
            s.x = fmaf(a, vm.x, s.x); s.y = fmaf(a, vm.y, s.y);
            s.z = fmaf(a, vm.z, s.z); s.w = fmaf(a, vm.w, s.w);
        }
        *reinterpret_cast<float4*>((which ? e2s : e1s) + n * PS + 4 * h4) = s;
    }
    if (tid < 4) {
        int i = tid;
        const float4* av = reinterpret_cast<const float4*>(aV[i]);
        const float4* bv = reinterpret_cast<const float4*>(sv[2 + (i & 1)]);
        float4 d4 = make_float4(0,0,0,0), a4 = d4, b4 = d4;
        #pragma unroll
        for (int t = 0; t < 16; t++) {
            float4 a = av[t], bb = bv[t];
            d4 = fma4(a, bb, d4); a4 = fma4(a, a, a4); b4 = fma4(bb, bb, b4);
        }
        float na = fmaxf(sqrtf(hsum4(a4)), 1e-8f);
        float nb = fmaxf(sqrtf(hsum4(b4)), 1e-8f);
        feat[256 + i] = hsum4(d4) / (na * nb);
    }
    __syncthreads();

    // Phase 4: max/mean pooling of e1/e2 + sv into feat
    if (tid < 128) {
        int which = tid >> 6, hh = tid & 63;
        const float* E = which ? e2s : e1s;
        float mx = -3.4e38f, sm = 0.f;
        #pragma unroll
        for (int n = 0; n < 16; n++) { float v = E[n * PS + hh]; mx = fmaxf(mx, v); sm += v; }
        feat[which * 128 + hh]      = mx;
        feat[which * 128 + 64 + hh] = sm * (1.f / 16.f);
    }
    feat[260 + tid] = sv[tid >> 6][tid & 63];
    __syncthreads();

    // Phase 5: fc0 + gelu (float4, 4-way split 128/128/128/132)
    {
        int j = tid >> 2, part = tid & 3;
        int off = part * 128;
        int n4 = (part == 3) ? 33 : 32;
        const float4* w  = reinterpret_cast<const float4*>(fc0_w + (size_t)j * 516 + off);
        const float4* fr = reinterpret_cast<const float4*>(feat + off);
        float4 acc = make_float4(0,0,0,0);
        #pragma unroll 8
        for (int t = 0; t < n4; t++) acc = fma4(w[t], fr[t], acc);
        float s = hsum4(acc);
        s += __shfl_xor_sync(0xffffffff, s, 1);
        s += __shfl_xor_sync(0xffffffff, s, 2);
        if (part == 0) h1[j] = gelu_f(fc0_b[j] + s);
    }
    __syncthreads();

    // Phase 6: fc1 + gelu + softmax
    if (tid == 0) {
        float l0 = fc1_b[0], l1 = fc1_b[1];
        #pragma unroll
        for (int j = 0; j < 64; j++) { l0 += h1[j] * fc1_w[j]; l1 += h1[j] * fc1_w[64 + j]; }
        l0 = gelu_f(l0); l1 = gelu_f(l1);
        float m = fmaxf(l0, l1);
        float ea = expf(l0 - m), eb = expf(l1 - m);
        float inv = 1.f / (ea + eb);
        out[b * 2 + 0] = ea * inv;
        out[b * 2 + 1] = eb * inv;
    }
}

// =====================================================================
typedef CUresult (*EncodeTiledFn)(
    CUtensorMap*, CUtensorMapDataType, cuuint32_t, void*,
    const cuuint64_t*, const cuuint64_t*, const cuuint32_t*, const cuuint32_t*,
    CUtensorMapInterleave, CUtensorMapSwizzle, CUtensorMapL2promotion,
    CUtensorMapFloatOOBfill);

extern "C" void kernel_launch(void* const* d_in, const int* in_sizes, int n_in,
                              void* d_out, int out_size)
{
    const float* token   = (const float*)d_in[0];
    const int*   kw_idx  = (const int*)  d_in[1];
    const float* q_w     = (const float*)d_in[2];
    const float* q_b     = (const float*)d_in[3];
    const float* k_w     = (const float*)d_in[4];
    const float* k_b     = (const float*)d_in[5];
    const float* v_w     = (const float*)d_in[6];
    const float* v_b     = (const float*)d_in[7];
    const float* mi_w    = (const float*)d_in[8];
    const float* mi_b    = (const float*)d_in[9];
    const float* inter_w = (const float*)d_in[10];
    const float* inter_b = (const float*)d_in[11];
    const float* fc0_w   = (const float*)d_in[12];
    const float* fc0_b   = (const float*)d_in[13];
    const float* fc1_w   = (const float*)d_in[14];
    const float* fc1_b   = (const float*)d_in[15];
    float* out = (float*)d_out;

    void* encPtr = nullptr;
    cudaDriverEntryPointQueryResult qr;
    cudaGetDriverEntryPointByVersion("cuTensorMapEncodeTiled", &encPtr, 12000,
                                     cudaEnableDefault, &qr);
    EncodeTiledFn enc = (EncodeTiledFn)encPtr;

    void* xAddr = nullptr;
    void* wAddr = nullptr;
    cudaGetSymbolAddress(&xAddr, g_Xb);
    cudaGetSymbolAddress(&wAddr, g_Wb);

    CUtensorMap tmA, tmB;
    {
        cuuint64_t dims[2]    = {D_, MTOT};
        cuuint64_t strides[1] = {D_ * 2};
        cuuint32_t box[2]     = {64, 64};
        cuuint32_t es[2]      = {1, 1};
        enc(&tmA, CU_TENSOR_MAP_DATA_TYPE_BFLOAT16, 2, xAddr,
            dims, strides, box, es,
            CU_TENSOR_MAP_INTERLEAVE_NONE, CU_TENSOR_MAP_SWIZZLE_128B,
            CU_TENSOR_MAP_L2_PROMOTION_L2_128B, CU_TENSOR_MAP_FLOAT_OOB_FILL_NONE);
    }
    {
        cuuint64_t dims[2]    = {D_, NTOT};
        cuuint64_t strides[1] = {D_ * 2};
        cuuint32_t box[2]     = {64, 128};
        cuuint32_t es[2]      = {1, 1};
        enc(&tmB, CU_TENSOR_MAP_DATA_TYPE_BFLOAT16, 2, wAddr,
            dims, strides, box, es,
            CU_TENSOR_MAP_INTERLEAVE_NONE, CU_TENSOR_MAP_SWIZZLE_128B,
            CU_TENSOR_MAP_L2_PROMOTION_L2_128B, CU_TENSOR_MAP_FLOAT_OOB_FILL_NONE);
    }

    cudaFuncSetAttribute(gemm_tc_kernel,
                         cudaFuncAttributeMaxDynamicSharedMemorySize, GEMM_SMEM);

    gather_pack_kernel<<<256 + 32, 512>>>(token, kw_idx, q_w, k_w, v_w, mi_w);
    gemm_tc_kernel<<<dim3(MTOT / 64, 2), 256, GEMM_SMEM>>>(tmA, tmB);
    head_kernel<<<B_, 256>>>(q_b, k_b, v_b, mi_b, inter_w, inter_b,
                             fc0_w, fc0_b, fc1_w, fc1_b, out);
}

// round 12
// speedup vs baseline: 2.7077x; 1.0010x over previous
#include <cuda_runtime.h>
#include <cuda.h>
#include <cuda_bf16.h>
#include <math.h>
#include <stdint.h>

// Problem constants
#define B_   128
#define S_   256
#define D_   1024
#define DH_  64
#define K_   8
#define L_   2
#define NROWS 18          // 16 gathered rows + vmax + vavg
#define MTOT (B_*2*NROWS) // 4608
#define NTOT 256          // q(64)|k(64)|v(64)|mi(64)

// -------- scratch (no allocations allowed) --------
__device__ uint16_t g_Xb[(size_t)MTOT * D_];   // gathered rows + pooled, bf16
__device__ uint16_t g_Wb[(size_t)NTOT * D_];   // packed weights q|k|v|mi, bf16
__device__ float    g_Y [(size_t)MTOT * NTOT]; // projection outputs (f32)

__device__ __forceinline__ uint2 f4_to_bf4(float4 v) {
    __nv_bfloat162 lo = __floats2bfloat162_rn(v.x, v.y);
    __nv_bfloat162 hi = __floats2bfloat162_rn(v.z, v.w);
    uint2 r;
    r.x = *reinterpret_cast<uint32_t*>(&lo);
    r.y = *reinterpret_cast<uint32_t*>(&hi);
    return r;
}

// =====================================================================
// Kernel 1: gather (blocks 0..255, 512 thr) + weight pack (256..287)
// Front-batched loads: all 8 LDG.128 issued before any convert/store,
// forcing high MLP (reg-allocation-driven).
// =====================================================================
__global__ void __launch_bounds__(512)
gather_pack_kernel(const float* __restrict__ token,
                   const int* __restrict__ kw_idx,
                   const float* __restrict__ wq, const float* __restrict__ wk,
                   const float* __restrict__ wv, const float* __restrict__ wmi)
{
    int tid = threadIdx.x;
    if (blockIdx.x >= 256) {
        int f4base = (blockIdx.x - 256) * 2048 + tid;
        float4 v[4];
        #pragma unroll
        for (int i = 0; i < 4; i++) {
            int f4 = f4base + i * 512;
            int wsel = f4 >> 14;
            const float* W = (wsel == 0) ? wq : (wsel == 1) ? wk :
                             (wsel == 2) ? wv : wmi;
            v[i] = reinterpret_cast<const float4*>(W)[f4 & 16383];
        }
        #pragma unroll
        for (int i = 0; i < 4; i++)
            reinterpret_cast<uint2*>(g_Wb)[f4base + i * 512] = f4_to_bf4(v[i]);
        return;
    }

    __shared__ int idx[K_];
    __shared__ float4 pmax[2][256];
    __shared__ float4 psum[2][256];

    int bs = blockIdx.x;
    int b = bs >> 1, s = bs & 1;
    if (tid < K_)
        idx[tid] = kw_idx[(b * 2 + (1 - s)) * K_ + tid];
    __syncthreads();

    int col = tid & 255;
    int rp  = tid >> 8;
    const float* tbase = token + (((size_t)b * 2 + s) * L_ + rp) * S_ * D_;
    uint16_t* Xrow = g_Xb + (size_t)bs * NROWS * D_;

    // ---- front-batched loads: 8 independent LDG.128 ----
    float4 vals[8];
    #pragma unroll
    for (int j = 0; j < 8; j++)
        vals[j] = reinterpret_cast<const float4*>(tbase + (size_t)idx[j] * D_)[col];

    // ---- convert + store + pool ----
    float4 mx = make_float4(-3.4e38f, -3.4e38f, -3.4e38f, -3.4e38f);
    float4 sm = make_float4(0.f, 0.f, 0.f, 0.f);
    #pragma unroll
    for (int j = 0; j < 8; j++) {
        float4 v = vals[j];
        int r = rp * 8 + j;
        reinterpret_cast<uint2*>(Xrow + (size_t)r * D_)[col] = f4_to_bf4(v);
        mx.x = fmaxf(mx.x, v.x); mx.y = fmaxf(mx.y, v.y);
        mx.z = fmaxf(mx.z, v.z); mx.w = fmaxf(mx.w, v.w);
        sm.x += v.x; sm.y += v.y; sm.z += v.z; sm.w += v.w;
    }
    pmax[rp][col] = mx;
    psum[rp][col] = sm;
    __syncthreads();

    if (tid < 256) {
        float4 m0 = pmax[0][col], m1 = pmax[1][col];
        float4 s0 = psum[0][col], s1 = psum[1][col];
        float4 M, S;
        M.x = fmaxf(m0.x, m1.x); M.y = fmaxf(m0.y, m1.y);
        M.z = fmaxf(m0.z, m1.z); M.w = fmaxf(m0.w, m1.w);
        S.x = (s0.x + s1.x) * (1.f/16.f);
        S.y = (s0.y + s1.y) * (1.f/16.f);
        S.z = (s0.z + s1.z) * (1.f/16.f);
        S.w = (s0.w + s1.w) * (1.f/16.f);
        reinterpret_cast<uint2*>(Xrow + (size_t)16 * D_)[col] = f4_to_bf4(M);
        reinterpret_cast<uint2*>(Xrow + (size_t)17 * D_)[col] = f4_to_bf4(S);
    }
}

// =====================================================================
// Kernel 2: bf16 tensor GEMM  g_Y[M,256] = X @ W^T   (R6 baseline)
// =====================================================================
#define A_BYTES (64 * 128)
#define B_BYTES (128 * 128)
#define STAGE_BYTES (A_BYTES + B_BYTES)
#define GEMM_SMEM (3 * STAGE_BYTES)

__device__ __forceinline__ void mbar_wait(uint32_t mbar, int phase) {
    asm volatile(
        "{\n\t.reg .pred P;\n"
        "W%=:\n\t"
        "mbarrier.try_wait.parity.acquire.cta.shared::cta.b64 P, [%0], %1, 0x989680;\n\t"
        "@P bra D%=;\n\t"
        "bra W%=;\n"
        "D%=:\n\t}"
        :: "r"(mbar), "r"(phase) : "memory");
}

__device__ __forceinline__ void tma_2d(uint32_t dst, const CUtensorMap* tm,
                                       int x, int y, uint32_t mbar) {
    asm volatile(
        "cp.async.bulk.tensor.2d.shared::cta.global.tile.mbarrier::complete_tx::bytes "
        "[%0], [%1, {%2, %3}], [%4];"
        :: "r"(dst), "l"(tm), "r"(x), "r"(y), "r"(mbar) : "memory");
}

__global__ void __launch_bounds__(256, 1)
gemm_tc_kernel(const __grid_constant__ CUtensorMap tmA,
               const __grid_constant__ CUtensorMap tmB)
{
    extern __shared__ __align__(1024) uint16_t smem_b[];
    __shared__ __align__(8) uint64_t mbar_s[6];

    const uint32_t smem_s = (uint32_t)__cvta_generic_to_shared(smem_b);
    const uint32_t mb     = (uint32_t)__cvta_generic_to_shared(mbar_s);

    const int tid  = threadIdx.x;
    const int lane = tid & 31;
    const int warp = tid >> 5;
    const int wm   = warp >> 2;
    const int wn   = warp & 3;
    const int m0   = blockIdx.x * 64;
    const int n0   = blockIdx.y * 128;

    if (tid == 0) {
        #pragma unroll
        for (int s = 0; s < 3; s++) {
            asm volatile("mbarrier.init.shared.b64 [%0], %1;" :: "r"(mb + s * 8), "r"(1) : "memory");
            asm volatile("mbarrier.init.shared.b64 [%0], %1;" :: "r"(mb + 24 + s * 8), "r"(256) : "memory");
        }
    }
    __syncthreads();

    if (tid == 0) {
        #pragma unroll
        for (int s = 0; s < 3; s++) {
            uint32_t fb = mb + s * 8;
            asm volatile("mbarrier.arrive.expect_tx.shared.b64 _, [%0], %1;"
                         :: "r"(fb), "r"(STAGE_BYTES) : "memory");
            uint32_t base = smem_s + s * STAGE_BYTES;
            tma_2d(base,           &tmA, s * 64, m0, fb);
            tma_2d(base + A_BYTES, &tmB, s * 64, n0, fb);
        }
    }

    float c[2][4][4];
    #pragma unroll
    for (int i = 0; i < 2; i++)
        #pragma unroll
        for (int j = 0; j < 4; j++)
            #pragma unroll
            for (int r = 0; r < 4; r++) c[i][j][r] = 0.f;

    const int j4   = lane >> 3;
    const int lr   = lane & 7;
    const int aRow = wm * 32 + (j4 & 1) * 8 + lr;
    const int aKj  = j4 >> 1;
    const int aSw  = aRow & 7;
    const int bRow = wn * 32 + (j4 >> 1) * 8 + lr;
    const int bKj  = j4 & 1;
    const int bSw  = bRow & 7;
    const uint32_t aByte0 = aRow * 128;
    const uint32_t aByte1 = (aRow + 16) * 128;
    const uint32_t bByte0 = bRow * 128;
    const uint32_t bByte1 = (bRow + 16) * 128;

    int cs = 0, cph = 0;
    int ps = 0, pep = 0;

    for (int kt = 0; kt < 16; kt++) {
        mbar_wait(mb + cs * 8, cph);

        const uint32_t As = smem_s + cs * STAGE_BYTES;
        const uint32_t Bs = As + A_BYTES;

        #pragma unroll
        for (int step = 0; step < 4; step++) {
            const int cA = (2 * step + aKj) ^ aSw;
            const int cB = (2 * step + bKj) ^ bSw;
            uint32_t a0[4], a1[4], b0[4], b1[4];
            {
                uint32_t addr = As + aByte0 + (cA << 4);
                asm volatile("ldmatrix.sync.aligned.m8n8.x4.shared.b16 {%0,%1,%2,%3}, [%4];"
                             : "=r"(a0[0]), "=r"(a0[1]), "=r"(a0[2]), "=r"(a0[3]) : "r"(addr));
            }
            {
                uint32_t addr = As + aByte1 + (cA << 4);
                asm volatile("ldmatrix.sync.aligned.m8n8.x4.shared.b16 {%0,%1,%2,%3}, [%4];"
                             : "=r"(a1[0]), "=r"(a1[1]), "=r"(a1[2]), "=r"(a1[3]) : "r"(addr));
            }
            {
                uint32_t addr = Bs + bByte0 + (cB << 4);
                asm volatile("ldmatrix.sync.aligned.m8n8.x4.shared.b16 {%0,%1,%2,%3}, [%4];"
                             : "=r"(b0[0]), "=r"(b0[1]), "=r"(b0[2]), "=r"(b0[3]) : "r"(addr));
            }
            {
                uint32_t addr = Bs + bByte1 + (cB << 4);
                asm volatile("ldmatrix.sync.aligned.m8n8.x4.shared.b16 {%0,%1,%2,%3}, [%4];"
                             : "=r"(b1[0]), "=r"(b1[1]), "=r"(b1[2]), "=r"(b1[3]) : "r"(addr));
            }
            #pragma unroll
            for (int mt = 0; mt < 2; mt++) {
                const uint32_t* a = mt ? a1 : a0;
                #pragma unroll
                for (int nt = 0; nt < 4; nt++) {
                    const uint32_t* bb = (nt < 2) ? &b0[(nt & 1) * 2] : &b1[(nt & 1) * 2];
                    asm volatile(
                        "mma.sync.aligned.m16n8k16.row.col.f32.bf16.bf16.f32 "
                        "{%0,%1,%2,%3}, {%4,%5,%6,%7}, {%8,%9}, {%0,%1,%2,%3};"
                        : "+f"(c[mt][nt][0]), "+f"(c[mt][nt][1]),
                          "+f"(c[mt][nt][2]), "+f"(c[mt][nt][3])
                        : "r"(a[0]), "r"(a[1]), "r"(a[2]), "r"(a[3]),
                          "r"(bb[0]), "r"(bb[1]));
                }
            }
        }

        asm volatile("mbarrier.arrive.shared.b64 _, [%0];" :: "r"(mb + 24 + cs * 8) : "memory");

        if (tid == 0 && kt + 3 < 16) {
            mbar_wait(mb + 24 + ps * 8, pep);
            uint32_t fb = mb + ps * 8;
            asm volatile("mbarrier.arrive.expect_tx.shared.b64 _, [%0], %1;"
                         :: "r"(fb), "r"(STAGE_BYTES) : "memory");
            uint32_t base = smem_s + ps * STAGE_BYTES;
            tma_2d(base,           &tmA, (kt + 3) * 64, m0, fb);
            tma_2d(base + A_BYTES, &tmB, (kt + 3) * 64, n0, fb);
            ps++; if (ps == 3) { ps = 0; pep ^= 1; }
        }

        cs++; if (cs == 3) { cs = 0; cph ^= 1; }
    }

    const int g  = lane >> 2;
    const int tg = lane & 3;
    #pragma unroll
    for (int mt = 0; mt < 2; mt++) {
        const int rA = m0 + wm * 32 + mt * 16 + g;
        #pragma unroll
        for (int nt = 0; nt < 4; nt++) {
            const int col = n0 + wn * 32 + nt * 8 + 2 * tg;
            *reinterpret_cast<float2*>(g_Y + (size_t)rA * NTOT + col) =
                make_float2(c[mt][nt][0], c[mt][nt][1]);
            *reinterpret_cast<float2*>(g_Y + (size_t)(rA + 8) * NTOT + col) =
                make_float2(c[mt][nt][2], c[mt][nt][3]);
        }
    }
}

// =====================================================================
// Kernel 3: per-b heads — vectorized, conflict-free (R11 version)
// =====================================================================
__device__ __forceinline__ float gelu_f(float x) {
    return 0.5f * x * (1.0f + erff(x * 0.70710678118654752440f));
}
__device__ __forceinline__ float4 fma4(float4 a, float4 b, float4 c) {
    return make_float4(fmaf(a.x,b.x,c.x), fmaf(a.y,b.y,c.y),
                       fmaf(a.z,b.z,c.z), fmaf(a.w,b.w,c.w));
}
__device__ __forceinline__ float hsum4(float4 a) { return (a.x+a.y)+(a.z+a.w); }

#define PS 68   // padded row stride (floats)

__global__ void __launch_bounds__(256)
head_kernel(const float* __restrict__ q_b, const float* __restrict__ k_b,
            const float* __restrict__ v_b, const float* __restrict__ mi_b,
            const float* __restrict__ inter_w, const float* __restrict__ inter_b,
            const float* __restrict__ fc0_w, const float* __restrict__ fc0_b,
            const float* __restrict__ fc1_w, const float* __restrict__ fc1_b,
            float* __restrict__ out)
{
    __shared__ __align__(16) float q0[16*PS], k0[16*PS], v0[16*PS];
    __shared__ __align__(16) float q1[16*PS], k1[16*PS], v1[16*PS];
    __shared__ __align__(16) float e1s[16*PS], e2s[16*PS];
    __shared__ __align__(16) float att[512];
    __shared__ __align__(16) float sv[4][64];
    __shared__ __align__(16) float aV[4][64];
    __shared__ __align__(16) float feat[520];
    __shared__ float h1[64];

    int b = blockIdx.x;
    int tid = threadIdx.x;
    const float* Y0 = g_Y + (size_t)(b * 2 + 0) * NROWS * NTOT;
    const float* Y1 = g_Y + (size_t)(b * 2 + 1) * NROWS * NTOT;

    {
        int n = tid >> 4, c = tid & 15;
        float4 bq = reinterpret_cast<const float4*>(q_b)[c];
        float4 bk = reinterpret_cast<const float4*>(k_b)[c];
        float4 bv = reinterpret_cast<const float4*>(v_b)[c];
        const float4* r0 = reinterpret_cast<const float4*>(Y0 + n * NTOT);
        const float4* r1 = reinterpret_cast<const float4*>(Y1 + n * NTOT);
        float4 v;
        v = r0[c];      *reinterpret_cast<float4*>(&q0[n*PS + 4*c]) = fma4(v, make_float4(1,1,1,1), bq);
        v = r0[16 + c]; *reinterpret_cast<float4*>(&k0[n*PS + 4*c]) = fma4(v, make_float4(1,1,1,1), bk);
        v = r0[32 + c]; *reinterpret_cast<float4*>(&v0[n*PS + 4*c]) = fma4(v, make_float4(1,1,1,1), bv);
        v = r1[c];      *reinterpret_cast<float4*>(&q1[n*PS + 4*c]) = fma4(v, make_float4(1,1,1,1), bq);
        v = r1[16 + c]; *reinterpret_cast<float4*>(&k1[n*PS + 4*c]) = fma4(v, make_float4(1,1,1,1), bk);
        v = r1[32 + c]; *reinterpret_cast<float4*>(&v1[n*PS + 4*c]) = fma4(v, make_float4(1,1,1,1), bv);
    }
    {
        int i = tid >> 6, h = tid & 63;
        const float* Yx = (i < 2) ? Y0 : Y1;
        sv[i][h] = Yx[(16 + (i & 1)) * NTOT + 192 + h] + mi_b[h];
    }
    __syncthreads();

    #pragma unroll
    for (int e = tid; e < 512; e += 256) {
        int which = e >> 8, n = (e >> 4) & 15, m = e & 15;
        const float4* qq = reinterpret_cast<const float4*>((which ? q1 : q0) + n * PS);
        const float4* kk = reinterpret_cast<const float4*>((which ? k0 : k1) + m * PS);
        float4 acc = make_float4(0,0,0,0);
        #pragma unroll
        for (int t = 0; t < 16; t++) acc = fma4(qq[t], kk[t], acc);
        att[e] = hsum4(acc) * 0.125f;
    }
    {
        int i = tid >> 6, j = tid & 63;
        const float4* w = reinterpret_cast<const float4*>(inter_w + ((size_t)i * 64 + j) * 64);
        const float4* src = reinterpret_cast<const float4*>(sv[i >> 1]);
        float4 acc = make_float4(0,0,0,0);
        #pragma unroll
        for (int t = 0; t < 16; t++) acc = fma4(w[t], src[t], acc);
        aV[i][j] = inter_b[i * 64 + j] + hsum4(acc);
    }
    __syncthreads();

    #pragma unroll
    for (int f = tid; f < 512; f += 256) {
        int which = f >> 8, n = (f >> 4) & 15, h4 = f & 15;
        const float* vv = which ? v0 : v1;
        const float* am = att + which * 256 + n * 16;
        float4 s = make_float4(0,0,0,0);
        #pragma unroll
        for (int m = 0; m < 16; m++) {
            float a = am[m];
            float4 vm = *reinterpret_cast<const float4*>(vv + m * PS + 4 * h4);
            s.x = fmaf(a, vm.x, s.x); s.y = fmaf(a, vm.y, s.y);
            s.z = fmaf(a, vm.z, s.z); s.w = fmaf(a, vm.w, s.w);
        }
        *reinterpret_cast<float4*>((which ? e2s : e1s) + n * PS + 4 * h4) = s;
    }
    if (tid < 4) {
        int i = tid;
        const float4* av = reinterpret_cast<const float4*>(aV[i]);
        const float4* bv = reinterpret_cast<const float4*>(sv[2 + (i & 1)]);
        float4 d4 = make_float4(0,0,0,0), a4 = d4, b4 = d4;
        #pragma unroll
        for (int t = 0; t < 16; t++) {
            float4 a = av[t], bb = bv[t];
            d4 = fma4(a, bb, d4); a4 = fma4(a, a, a4); b4 = fma4(bb, bb, b4);
        }
        float na = fmaxf(sqrtf(hsum4(a4)), 1e-8f);
        float nb = fmaxf(sqrtf(hsum4(b4)), 1e-8f);
        feat[256 + i] = hsum4(d4) / (na * nb);
    }
    __syncthreads();

    if (tid < 128) {
        int which = tid >> 6, hh = tid & 63;
        const float* E = which ? e2s : e1s;
        float mx = -3.4e38f, sm = 0.f;
        #pragma unroll
        for (int n = 0; n < 16; n++) { float v = E[n * PS + hh]; mx = fmaxf(mx, v); sm += v; }
        feat[which * 128 + hh]      = mx;
        feat[which * 128 + 64 + hh] = sm * (1.f / 16.f);
    }
    feat[260 + tid] = sv[tid >> 6][tid & 63];
    __syncthreads();

    {
        int j = tid >> 2, part = tid & 3;
        int off = part * 128;
        int n4 = (part == 3) ? 33 : 32;
        const float4* w  = reinterpret_cast<const float4*>(fc0_w + (size_t)j * 516 + off);
        const float4* fr = reinterpret_cast<const float4*>(feat + off);
        float4 acc = make_float4(0,0,0,0);
        #pragma unroll 8
        for (int t = 0; t < n4; t++) acc = fma4(w[t], fr[t], acc);
        float s = hsum4(acc);
        s += __shfl_xor_sync(0xffffffff, s, 1);
        s += __shfl_xor_sync(0xffffffff, s, 2);
        if (part == 0) h1[j] = gelu_f(fc0_b[j] + s);
    }
    __syncthreads();

    if (tid == 0) {
        float l0 = fc1_b[0], l1 = fc1_b[1];
        #pragma unroll
        for (int j = 0; j < 64; j++) { l0 += h1[j] * fc1_w[j]; l1 += h1[j] * fc1_w[64 + j]; }
        l0 = gelu_f(l0); l1 = gelu_f(l1);
        float m = fmaxf(l0, l1);
        float ea = expf(l0 - m), eb = expf(l1 - m);
        float inv = 1.f / (ea + eb);
        out[b * 2 + 0] = ea * inv;
        out[b * 2 + 1] = eb * inv;
    }
}

// =====================================================================
typedef CUresult (*EncodeTiledFn)(
    CUtensorMap*, CUtensorMapDataType, cuuint32_t, void*,
    const cuuint64_t*, const cuuint64_t*, const cuuint32_t*, const cuuint32_t*,
    CUtensorMapInterleave, CUtensorMapSwizzle, CUtensorMapL2promotion,
    CUtensorMapFloatOOBfill);

extern "C" void kernel_launch(void* const* d_in, const int* in_sizes, int n_in,
                              void* d_out, int out_size)
{
    const float* token   = (const float*)d_in[0];
    const int*   kw_idx  = (const int*)  d_in[1];
    const float* q_w     = (const float*)d_in[2];
    const float* q_b     = (const float*)d_in[3];
    const float* k_w     = (const float*)d_in[4];
    const float* k_b     = (const float*)d_in[5];
    const float* v_w     = (const float*)d_in[6];
    const float* v_b     = (const float*)d_in[7];
    const float* mi_w    = (const float*)d_in[8];
    const float* mi_b    = (const float*)d_in[9];
    const float* inter_w = (const float*)d_in[10];
    const float* inter_b = (const float*)d_in[11];
    const float* fc0_w   = (const float*)d_in[12];
    const float* fc0_b   = (const float*)d_in[13];
    const float* fc1_w   = (const float*)d_in[14];
    const float* fc1_b   = (const float*)d_in[15];
    float* out = (float*)d_out;

    void* encPtr = nullptr;
    cudaDriverEntryPointQueryResult qr;
    cudaGetDriverEntryPointByVersion("cuTensorMapEncodeTiled", &encPtr, 12000,
                                     cudaEnableDefault, &qr);
    EncodeTiledFn enc = (EncodeTiledFn)encPtr;

    void* xAddr = nullptr;
    void* wAddr = nullptr;
    cudaGetSymbolAddress(&xAddr, g_Xb);
    cudaGetSymbolAddress(&wAddr, g_Wb);

    CUtensorMap tmA, tmB;
    {
        cuuint64_t dims[2]    = {D_, MTOT};
        cuuint64_t strides[1] = {D_ * 2};
        cuuint32_t box[2]     = {64, 64};
        cuuint32_t es[2]      = {1, 1};
        enc(&tmA, CU_TENSOR_MAP_DATA_TYPE_BFLOAT16, 2, xAddr,
            dims, strides, box, es,
            CU_TENSOR_MAP_INTERLEAVE_NONE, CU_TENSOR_MAP_SWIZZLE_128B,
            CU_TENSOR_MAP_L2_PROMOTION_L2_128B, CU_TENSOR_MAP_FLOAT_OOB_FILL_NONE);
    }
    {
        cuuint64_t dims[2]    = {D_, NTOT};
        cuuint64_t strides[1] = {D_ * 2};
        cuuint32_t box[2]     = {64, 128};
        cuuint32_t es[2]      = {1, 1};
        enc(&tmB, CU_TENSOR_MAP_DATA_TYPE_BFLOAT16, 2, wAddr,
            dims, strides, box, es,
            CU_TENSOR_MAP_INTERLEAVE_NONE, CU_TENSOR_MAP_SWIZZLE_128B,
            CU_TENSOR_MAP_L2_PROMOTION_L2_128B, CU_TENSOR_MAP_FLOAT_OOB_FILL_NONE);
    }

    cudaFuncSetAttribute(gemm_tc_kernel,
                         cudaFuncAttributeMaxDynamicSharedMemorySize, GEMM_SMEM);

    gather_pack_kernel<<<256 + 32, 512>>>(token, kw_idx, q_w, k_w, v_w, mi_w);
    gemm_tc_kernel<<<dim3(MTOT / 64, 2), 256, GEMM_SMEM>>>(tmA, tmB);
    head_kernel<<<B_, 256>>>(q_b, k_b, v_b, mi_b, inter_w, inter_b,
                             fc0_w, fc0_b, fc1_w, fc1_b, out);
}

// round 13
// speedup vs baseline: 2.8664x; 1.0586x over previous
#include <cuda_runtime.h>
#include <cuda.h>
#include <cuda_bf16.h>
#include <math.h>
#include <stdint.h>

// Problem constants
#define B_   128
#define S_   256
#define D_   1024
#define K_   8
#define L_   2

// -------- scratch (no allocations allowed) --------
__device__ uint16_t g_X16[(size_t)4096 * D_];  // gathered data rows, bf16
__device__ uint16_t g_Xp [(size_t)512 * D_];   // pooled rows bf16 (bs*2+{max,avg})
__device__ uint16_t g_Wb [(size_t)256 * D_];   // packed weights q|k|v|mi, bf16
__device__ float    g_Yqkv[(size_t)4096 * 192];
__device__ float    g_Ymi [(size_t)512 * 64];

__device__ __forceinline__ uint2 f4_to_bf4(float4 v) {
    __nv_bfloat162 lo = __floats2bfloat162_rn(v.x, v.y);
    __nv_bfloat162 hi = __floats2bfloat162_rn(v.z, v.w);
    uint2 r;
    r.x = *reinterpret_cast<uint32_t*>(&lo);
    r.y = *reinterpret_cast<uint32_t*>(&hi);
    return r;
}

// =====================================================================
// Kernel 1: gather (blocks 0..255, 512 thr) + weight pack (256..287)
// =====================================================================
__global__ void __launch_bounds__(512)
gather_pack_kernel(const float* __restrict__ token,
                   const int* __restrict__ kw_idx,
                   const float* __restrict__ wq, const float* __restrict__ wk,
                   const float* __restrict__ wv, const float* __restrict__ wmi)
{
    int tid = threadIdx.x;
    if (blockIdx.x >= 256) {
        int f4base = (blockIdx.x - 256) * 2048 + tid;
        #pragma unroll
        for (int i = 0; i < 4; i++) {
            int f4 = f4base + i * 512;
            int wsel = f4 >> 14;
            const float* W = (wsel == 0) ? wq : (wsel == 1) ? wk :
                             (wsel == 2) ? wv : wmi;
            float4 v = reinterpret_cast<const float4*>(W)[f4 & 16383];
            reinterpret_cast<uint2*>(g_Wb)[f4] = f4_to_bf4(v);
        }
        return;
    }

    __shared__ int idx[K_];
    __shared__ float4 pmax[2][256];
    __shared__ float4 psum[2][256];

    int bs = blockIdx.x;
    int b = bs >> 1, s = bs & 1;
    if (tid < K_)
        idx[tid] = kw_idx[(b * 2 + (1 - s)) * K_ + tid];
    __syncthreads();

    int col = tid & 255;
    int rp  = tid >> 8;
    const float* tbase = token + (((size_t)b * 2 + s) * L_ + rp) * S_ * D_;
    uint16_t* Xrow = g_X16 + (size_t)bs * 16 * D_;

    float4 mx = make_float4(-3.4e38f, -3.4e38f, -3.4e38f, -3.4e38f);
    float4 sm = make_float4(0.f, 0.f, 0.f, 0.f);

    #pragma unroll
    for (int j = 0; j < 8; j++) {
        int r = rp * 8 + j;
        float4 v = reinterpret_cast<const float4*>(tbase + (size_t)idx[j] * D_)[col];
        reinterpret_cast<uint2*>(Xrow + (size_t)r * D_)[col] = f4_to_bf4(v);
        mx.x = fmaxf(mx.x, v.x); mx.y = fmaxf(mx.y, v.y);
        mx.z = fmaxf(mx.z, v.z); mx.w = fmaxf(mx.w, v.w);
        sm.x += v.x; sm.y += v.y; sm.z += v.z; sm.w += v.w;
    }
    pmax[rp][col] = mx;
    psum[rp][col] = sm;
    __syncthreads();

    if (tid < 256) {
        float4 m0 = pmax[0][col], m1 = pmax[1][col];
        float4 s0 = psum[0][col], s1 = psum[1][col];
        float4 M, S;
        M.x = fmaxf(m0.x, m1.x); M.y = fmaxf(m0.y, m1.y);
        M.z = fmaxf(m0.z, m1.z); M.w = fmaxf(m0.w, m1.w);
        S.x = (s0.x + s1.x) * (1.f/16.f);
        S.y = (s0.y + s1.y) * (1.f/16.f);
        S.z = (s0.z + s1.z) * (1.f/16.f);
        S.w = (s0.w + s1.w) * (1.f/16.f);
        uint16_t* Xp = g_Xp + (size_t)bs * 2 * D_;
        reinterpret_cast<uint2*>(Xp)[col]      = f4_to_bf4(M);
        reinterpret_cast<uint2*>(Xp + D_)[col] = f4_to_bf4(S);
    }
}

// =====================================================================
// Kernel 2: bf16 mma GEMM, two block types:
//  blocks 0..127 : qkv — 32x192 tile over g_X16 (M=4096, N=192)
//  blocks 128..135: mi — 64x64 tile over g_Xp  (M=512,  N=64 @W192)
// TMA SW128 3-stage ring, ldmatrix.x4, mma.m16n8k16 f32acc.
// =====================================================================
#define QA_ST  4096                   // 32 rows x 128B
#define QB_ST  24576                  // 192 rows x 128B
#define QSTG   (QA_ST + QB_ST)        // 28672
#define MA_ST  8192                   // 64 rows
#define MB_ST  8192                   // 64 rows
#define MSTG   (MA_ST + MB_ST)        // 16384
#define GEMM_SMEM (3 * QSTG)          // 86016

__device__ __forceinline__ void mbar_wait(uint32_t mbar, int phase) {
    asm volatile(
        "{\n\t.reg .pred P;\n"
        "W%=:\n\t"
        "mbarrier.try_wait.parity.acquire.cta.shared::cta.b64 P, [%0], %1, 0x989680;\n\t"
        "@P bra D%=;\n\t"
        "bra W%=;\n"
        "D%=:\n\t}"
        :: "r"(mbar), "r"(phase) : "memory");
}

__device__ __forceinline__ void tma_2d(uint32_t dst, const CUtensorMap* tm,
                                       int x, int y, uint32_t mbar) {
    asm volatile(
        "cp.async.bulk.tensor.2d.shared::cta.global.tile.mbarrier::complete_tx::bytes "
        "[%0], [%1, {%2, %3}], [%4];"
        :: "r"(dst), "l"(tm), "r"(x), "r"(y), "r"(mbar) : "memory");
}

#define LDMX4(dst, addr) \
    asm volatile("ldmatrix.sync.aligned.m8n8.x4.shared.b16 {%0,%1,%2,%3}, [%4];" \
                 : "=r"((dst)[0]), "=r"((dst)[1]), "=r"((dst)[2]), "=r"((dst)[3]) : "r"(addr))

#define MMA16816(c, a, b0r, b1r) \
    asm volatile("mma.sync.aligned.m16n8k16.row.col.f32.bf16.bf16.f32 " \
                 "{%0,%1,%2,%3}, {%4,%5,%6,%7}, {%8,%9}, {%0,%1,%2,%3};" \
                 : "+f"((c)[0]), "+f"((c)[1]), "+f"((c)[2]), "+f"((c)[3]) \
                 : "r"((a)[0]), "r"((a)[1]), "r"((a)[2]), "r"((a)[3]), \
                   "r"(b0r), "r"(b1r))

__global__ void __launch_bounds__(256, 1)
gemm_tc_kernel(const __grid_constant__ CUtensorMap tmX16,
               const __grid_constant__ CUtensorMap tmXp,
               const __grid_constant__ CUtensorMap tmW192,
               const __grid_constant__ CUtensorMap tmW64)
{
    extern __shared__ __align__(1024) uint16_t smem_b[];
    __shared__ __align__(8) uint64_t mbar_s[6];   // full[0..2], empty[0..2]

    const uint32_t smem_s = (uint32_t)__cvta_generic_to_shared(smem_b);
    const uint32_t mb     = (uint32_t)__cvta_generic_to_shared(mbar_s);

    const int tid  = threadIdx.x;
    const int lane = tid & 31;
    const int warp = tid >> 5;
    const bool isMi = (blockIdx.x >= 128);

    if (tid == 0) {
        #pragma unroll
        for (int s = 0; s < 3; s++) {
            asm volatile("mbarrier.init.shared.b64 [%0], %1;" :: "r"(mb + s * 8), "r"(1) : "memory");
            asm volatile("mbarrier.init.shared.b64 [%0], %1;" :: "r"(mb + 24 + s * 8), "r"(256) : "memory");
        }
    }
    __syncthreads();

    const int j4 = lane >> 3;
    const int lr = lane & 7;
    const int g  = lane >> 2;
    const int tg = lane & 3;

    if (!isMi) {
        // ---------- qkv: 32x192 tile ----------
        const int m0 = blockIdx.x * 32;
        const int wm = warp >> 2;      // 0..1 (16 rows)
        const int wn = warp & 3;       // 0..3 (48 cols)
        const int stg = QSTG, aBytes = QA_ST;

        if (tid == 0) {
            #pragma unroll
            for (int s = 0; s < 3; s++) {
                uint32_t fb = mb + s * 8;
                asm volatile("mbarrier.arrive.expect_tx.shared.b64 _, [%0], %1;"
                             :: "r"(fb), "r"(stg) : "memory");
                uint32_t base = smem_s + s * stg;
                tma_2d(base,          &tmX16, s * 64, m0, fb);
                tma_2d(base + aBytes, &tmW192, s * 64, 0, fb);
            }
        }

        float c[6][4];
        #pragma unroll
        for (int j = 0; j < 6; j++)
            #pragma unroll
            for (int r = 0; r < 4; r++) c[j][r] = 0.f;

        const int aRow = wm * 16 + (j4 & 1) * 8 + lr;
        const int aKj  = j4 >> 1;
        const int aSw  = aRow & 7;
        const uint32_t aByte = aRow * 128;
        const int bKj  = j4 & 1;
        const int bSw  = lr;           // ((j4>>1)*8 + lr) & 7 == lr
        uint32_t bByte[3];
        #pragma unroll
        for (int t = 0; t < 3; t++)
            bByte[t] = (wn * 48 + t * 16 + (j4 >> 1) * 8 + lr) * 128;

        int cs = 0, cph = 0, ps = 0, pep = 0;
        for (int kt = 0; kt < 16; kt++) {
            mbar_wait(mb + cs * 8, cph);
            const uint32_t As = smem_s + cs * stg;
            const uint32_t Bs = As + aBytes;

            #pragma unroll
            for (int step = 0; step < 4; step++) {
                const int cA = (2 * step + aKj) ^ aSw;
                const int cB = (2 * step + bKj) ^ bSw;
                uint32_t a[4], bfr[3][4];
                LDMX4(a, As + aByte + (cA << 4));
                #pragma unroll
                for (int t = 0; t < 3; t++)
                    LDMX4(bfr[t], Bs + bByte[t] + (cB << 4));
                #pragma unroll
                for (int nt = 0; nt < 6; nt++) {
                    const uint32_t* bb = &bfr[nt >> 1][(nt & 1) * 2];
                    MMA16816(c[nt], a, bb[0], bb[1]);
                }
            }

            asm volatile("mbarrier.arrive.shared.b64 _, [%0];" :: "r"(mb + 24 + cs * 8) : "memory");

            if (tid == 0 && kt + 3 < 16) {
                mbar_wait(mb + 24 + ps * 8, pep);
                uint32_t fb = mb + ps * 8;
                asm volatile("mbarrier.arrive.expect_tx.shared.b64 _, [%0], %1;"
                             :: "r"(fb), "r"(stg) : "memory");
                uint32_t base = smem_s + ps * stg;
                tma_2d(base,          &tmX16, (kt + 3) * 64, m0, fb);
                tma_2d(base + aBytes, &tmW192, (kt + 3) * 64, 0, fb);
                ps++; if (ps == 3) { ps = 0; pep ^= 1; }
            }
            cs++; if (cs == 3) { cs = 0; cph ^= 1; }
        }

        const int rA = m0 + wm * 16 + g;
        #pragma unroll
        for (int nt = 0; nt < 6; nt++) {
            const int col = wn * 48 + nt * 8 + 2 * tg;
            *reinterpret_cast<float2*>(g_Yqkv + (size_t)rA * 192 + col) =
                make_float2(c[nt][0], c[nt][1]);
            *reinterpret_cast<float2*>(g_Yqkv + (size_t)(rA + 8) * 192 + col) =
                make_float2(c[nt][2], c[nt][3]);
        }
    } else {
        // ---------- mi: 64x64 tile over pooled rows ----------
        const int m0 = (blockIdx.x - 128) * 64;
        const int wm = warp >> 2;      // 0..1 (32 rows)
        const int wn = warp & 3;       // 0..3 (16 cols)
        const int stg = MSTG, aBytes = MA_ST;

        if (tid == 0) {
            #pragma unroll
            for (int s = 0; s < 3; s++) {
                uint32_t fb = mb + s * 8;
                asm volatile("mbarrier.arrive.expect_tx.shared.b64 _, [%0], %1;"
                             :: "r"(fb), "r"(stg) : "memory");
                uint32_t base = smem_s + s * stg;
                tma_2d(base,          &tmXp, s * 64, m0, fb);
                tma_2d(base + aBytes, &tmW64, s * 64, 192, fb);
            }
        }

        float c[2][2][4];
        #pragma unroll
        for (int i = 0; i < 2; i++)
            #pragma unroll
            for (int j = 0; j < 2; j++)
                #pragma unroll
                for (int r = 0; r < 4; r++) c[i][j][r] = 0.f;

        const int aRow = wm * 32 + (j4 & 1) * 8 + lr;
        const int aKj  = j4 >> 1;
        const int aSw  = aRow & 7;
        const uint32_t aByte0 = aRow * 128;
        const uint32_t aByte1 = (aRow + 16) * 128;
        const int bRow = wn * 16 + (j4 >> 1) * 8 + lr;
        const int bKj  = j4 & 1;
        const int bSw  = bRow & 7;
        const uint32_t bByte = bRow * 128;

        int cs = 0, cph = 0, ps = 0, pep = 0;
        for (int kt = 0; kt < 16; kt++) {
            mbar_wait(mb + cs * 8, cph);
            const uint32_t As = smem_s + cs * stg;
            const uint32_t Bs = As + aBytes;

            #pragma unroll
            for (int step = 0; step < 4; step++) {
                const int cA = (2 * step + aKj) ^ aSw;
                const int cB = (2 * step + bKj) ^ bSw;
                uint32_t a0[4], a1[4], bb[4];
                LDMX4(a0, As + aByte0 + (cA << 4));
                LDMX4(a1, As + aByte1 + (cA << 4));
                LDMX4(bb, Bs + bByte + (cB << 4));
                #pragma unroll
                for (int mt = 0; mt < 2; mt++) {
                    const uint32_t* a = mt ? a1 : a0;
                    #pragma unroll
                    for (int nt = 0; nt < 2; nt++)
                        MMA16816(c[mt][nt], a, bb[nt*2], bb[nt*2+1]);
                }
            }

            asm volatile("mbarrier.arrive.shared.b64 _, [%0];" :: "r"(mb + 24 + cs * 8) : "memory");

            if (tid == 0 && kt + 3 < 16) {
                mbar_wait(mb + 24 + ps * 8, pep);
                uint32_t fb = mb + ps * 8;
                asm volatile("mbarrier.arrive.expect_tx.shared.b64 _, [%0], %1;"
                             :: "r"(fb), "r"(stg) : "memory");
                uint32_t base = smem_s + ps * stg;
                tma_2d(base,          &tmXp, (kt + 3) * 64, m0, fb);
                tma_2d(base + aBytes, &tmW64, (kt + 3) * 64, 192, fb);
                ps++; if (ps == 3) { ps = 0; pep ^= 1; }
            }
            cs++; if (cs == 3) { cs = 0; cph ^= 1; }
        }

        #pragma unroll
        for (int mt = 0; mt < 2; mt++) {
            const int rA = m0 + wm * 32 + mt * 16 + g;
            #pragma unroll
            for (int nt = 0; nt < 2; nt++) {
                const int col = wn * 16 + nt * 8 + 2 * tg;
                *reinterpret_cast<float2*>(g_Ymi + (size_t)rA * 64 + col) =
                    make_float2(c[mt][nt][0], c[mt][nt][1]);
                *reinterpret_cast<float2*>(g_Ymi + (size_t)(rA + 8) * 64 + col) =
                    make_float2(c[mt][nt][2], c[mt][nt][3]);
            }
        }
    }
}

// =====================================================================
// Kernel 3: per-b heads — vectorized (R11), Y stride 192, sv from g_Ymi
// =====================================================================
__device__ __forceinline__ float gelu_f(float x) {
    return 0.5f * x * (1.0f + erff(x * 0.70710678118654752440f));
}
__device__ __forceinline__ float4 fma4(float4 a, float4 b, float4 c) {
    return make_float4(fmaf(a.x,b.x,c.x), fmaf(a.y,b.y,c.y),
                       fmaf(a.z,b.z,c.z), fmaf(a.w,b.w,c.w));
}
__device__ __forceinline__ float hsum4(float4 a) { return (a.x+a.y)+(a.z+a.w); }

#define PS 68

__global__ void __launch_bounds__(256)
head_kernel(const float* __restrict__ q_b, const float* __restrict__ k_b,
            const float* __restrict__ v_b, const float* __restrict__ mi_b,
            const float* __restrict__ inter_w, const float* __restrict__ inter_b,
            const float* __restrict__ fc0_w, const float* __restrict__ fc0_b,
            const float* __restrict__ fc1_w, const float* __restrict__ fc1_b,
            float* __restrict__ out)
{
    __shared__ __align__(16) float q0[16*PS], k0[16*PS], v0[16*PS];
    __shared__ __align__(16) float q1[16*PS], k1[16*PS], v1[16*PS];
    __shared__ __align__(16) float e1s[16*PS], e2s[16*PS];
    __shared__ __align__(16) float att[512];
    __shared__ __align__(16) float sv[4][64];
    __shared__ __align__(16) float aV[4][64];
    __shared__ __align__(16) float feat[520];
    __shared__ float h1[64];

    int b = blockIdx.x;
    int tid = threadIdx.x;
    const float* Y0 = g_Yqkv + (size_t)(b * 2 + 0) * 16 * 192;
    const float* Y1 = g_Yqkv + (size_t)(b * 2 + 1) * 16 * 192;

    {
        int n = tid >> 4, c = tid & 15;
        float4 bq = reinterpret_cast<const float4*>(q_b)[c];
        float4 bk = reinterpret_cast<const float4*>(k_b)[c];
        float4 bv = reinterpret_cast<const float4*>(v_b)[c];
        const float4* r0 = reinterpret_cast<const float4*>(Y0 + n * 192);
        const float4* r1 = reinterpret_cast<const float4*>(Y1 + n * 192);
        float4 v;
        v = r0[c];      *reinterpret_cast<float4*>(&q0[n*PS + 4*c]) = fma4(v, make_float4(1,1,1,1), bq);
        v = r0[16 + c]; *reinterpret_cast<float4*>(&k0[n*PS + 4*c]) = fma4(v, make_float4(1,1,1,1), bk);
        v = r0[32 + c]; *reinterpret_cast<float4*>(&v0[n*PS + 4*c]) = fma4(v, make_float4(1,1,1,1), bv);
        v = r1[c];      *reinterpret_cast<float4*>(&q1[n*PS + 4*c]) = fma4(v, make_float4(1,1,1,1), bq);
        v = r1[16 + c]; *reinterpret_cast<float4*>(&k1[n*PS + 4*c]) = fma4(v, make_float4(1,1,1,1), bk);
        v = r1[32 + c]; *reinterpret_cast<float4*>(&v1[n*PS + 4*c]) = fma4(v, make_float4(1,1,1,1), bv);
    }
    {
        int i = tid >> 6, h = tid & 63;
        sv[i][h] = g_Ymi[(size_t)(b * 4 + i) * 64 + h] + mi_b[h];
    }
    __syncthreads();

    #pragma unroll
    for (int e = tid; e < 512; e += 256) {
        int which = e >> 8, n = (e >> 4) & 15, m = e & 15;
        const float4* qq = reinterpret_cast<const float4*>((which ? q1 : q0) + n * PS);
        const float4* kk = reinterpret_cast<const float4*>((which ? k0 : k1) + m * PS);
        float4 acc = make_float4(0,0,0,0);
        #pragma unroll
        for (int t = 0; t < 16; t++) acc = fma4(qq[t], kk[t], acc);
        att[e] = hsum4(acc) * 0.125f;
    }
    {
        int i = tid >> 6, j = tid & 63;
        const float4* w = reinterpret_cast<const float4*>(inter_w + ((size_t)i * 64 + j) * 64);
        const float4* src = reinterpret_cast<const float4*>(sv[i >> 1]);
        float4 acc = make_float4(0,0,0,0);
        #pragma unroll
        for (int t = 0; t < 16; t++) acc = fma4(w[t], src[t], acc);
        aV[i][j] = inter_b[i * 64 + j] + hsum4(acc);
    }
    __syncthreads();

    #pragma unroll
    for (int f = tid; f < 512; f += 256) {
        int which = f >> 8, n = (f >> 4) & 15, h4 = f & 15;
        const float* vv = which ? v0 : v1;
        const float* am = att + which * 256 + n * 16;
        float4 s = make_float4(0,0,0,0);
        #pragma unroll
        for (int m = 0; m < 16; m++) {
            float a = am[m];
            float4 vm = *reinterpret_cast<const float4*>(vv + m * PS + 4 * h4);
            s.x = fmaf(a, vm.x, s.x); s.y = fmaf(a, vm.y, s.y);
            s.z = fmaf(a, vm.z, s.z); s.w = fmaf(a, vm.w, s.w);
        }
        *reinterpret_cast<float4*>((which ? e2s : e1s) + n * PS + 4 * h4) = s;
    }
    if (tid < 4) {
        int i = tid;
        const float4* av = reinterpret_cast<const float4*>(aV[i]);
        const float4* bv = reinterpret_cast<const float4*>(sv[2 + (i & 1)]);
        float4 d4 = make_float4(0,0,0,0), a4 = d4, b4 = d4;
        #pragma unroll
        for (int t = 0; t < 16; t++) {
            float4 a = av[t], bb = bv[t];
            d4 = fma4(a, bb, d4); a4 = fma4(a, a, a4); b4 = fma4(bb, bb, b4);
        }
        float na = fmaxf(sqrtf(hsum4(a4)), 1e-8f);
        float nb = fmaxf(sqrtf(hsum4(b4)), 1e-8f);
        feat[256 + i] = hsum4(d4) / (na * nb);
    }
    __syncthreads();

    if (tid < 128) {
        int which = tid >> 6, hh = tid & 63;
        const float* E = which ? e2s : e1s;
        float mx = -3.4e38f, sm = 0.f;
        #pragma unroll
        for (int n = 0; n < 16; n++) { float v = E[n * PS + hh]; mx = fmaxf(mx, v); sm += v; }
        feat[which * 128 + hh]      = mx;
        feat[which * 128 + 64 + hh] = sm * (1.f / 16.f);
    }
    feat[260 + tid] = sv[tid >> 6][tid & 63];
    __syncthreads();

    {
        int j = tid >> 2, part = tid & 3;
        int off = part * 128;
        int n4 = (part == 3) ? 33 : 32;
        const float4* w  = reinterpret_cast<const float4*>(fc0_w + (size_t)j * 516 + off);
        const float4* fr = reinterpret_cast<const float4*>(feat + off);
        float4 acc = make_float4(0,0,0,0);
        #pragma unroll 8
        for (int t = 0; t < n4; t++) acc = fma4(w[t], fr[t], acc);
        float s = hsum4(acc);
        s += __shfl_xor_sync(0xffffffff, s, 1);
        s += __shfl_xor_sync(0xffffffff, s, 2);
        if (part == 0) h1[j] = gelu_f(fc0_b[j] + s);
    }
    __syncthreads();

    if (tid == 0) {
        float l0 = fc1_b[0], l1 = fc1_b[1];
        #pragma unroll
        for (int j = 0; j < 64; j++) { l0 += h1[j] * fc1_w[j]; l1 += h1[j] * fc1_w[64 + j]; }
        l0 = gelu_f(l0); l1 = gelu_f(l1);
        float m = fmaxf(l0, l1);
        float ea = expf(l0 - m), eb = expf(l1 - m);
        float inv = 1.f / (ea + eb);
        out[b * 2 + 0] = ea * inv;
        out[b * 2 + 1] = eb * inv;
    }
}

// =====================================================================
typedef CUresult (*EncodeTiledFn)(
    CUtensorMap*, CUtensorMapDataType, cuuint32_t, void*,
    const cuuint64_t*, const cuuint64_t*, const cuuint32_t*, const cuuint32_t*,
    CUtensorMapInterleave, CUtensorMapSwizzle, CUtensorMapL2promotion,
    CUtensorMapFloatOOBfill);

static void make_map(EncodeTiledFn enc, CUtensorMap* tm, void* addr,
                     unsigned rows, unsigned boxRows) {
    cuuint64_t dims[2]    = {D_, rows};
    cuuint64_t strides[1] = {D_ * 2};
    cuuint32_t box[2]     = {64, boxRows};
    cuuint32_t es[2]      = {1, 1};
    enc(tm, CU_TENSOR_MAP_DATA_TYPE_BFLOAT16, 2, addr,
        dims, strides, box, es,
        CU_TENSOR_MAP_INTERLEAVE_NONE, CU_TENSOR_MAP_SWIZZLE_128B,
        CU_TENSOR_MAP_L2_PROMOTION_L2_128B, CU_TENSOR_MAP_FLOAT_OOB_FILL_NONE);
}

extern "C" void kernel_launch(void* const* d_in, const int* in_sizes, int n_in,
                              void* d_out, int out_size)
{
    const float* token   = (const float*)d_in[0];
    const int*   kw_idx  = (const int*)  d_in[1];
    const float* q_w     = (const float*)d_in[2];
    const float* q_b     = (const float*)d_in[3];
    const float* k_w     = (const float*)d_in[4];
    const float* k_b     = (const float*)d_in[5];
    const float* v_w     = (const float*)d_in[6];
    const float* v_b     = (const float*)d_in[7];
    const float* mi_w    = (const float*)d_in[8];
    const float* mi_b    = (const float*)d_in[9];
    const float* inter_w = (const float*)d_in[10];
    const float* inter_b = (const float*)d_in[11];
    const float* fc0_w   = (const float*)d_in[12];
    const float* fc0_b   = (const float*)d_in[13];
    const float* fc1_w   = (const float*)d_in[14];
    const float* fc1_b   = (const float*)d_in[15];
    float* out = (float*)d_out;

    void* encPtr = nullptr;
    cudaDriverEntryPointQueryResult qr;
    cudaGetDriverEntryPointByVersion("cuTensorMapEncodeTiled", &encPtr, 12000,
                                     cudaEnableDefault, &qr);
    EncodeTiledFn enc = (EncodeTiledFn)encPtr;

    void *x16Addr = nullptr, *xpAddr = nullptr, *wAddr = nullptr;
    cudaGetSymbolAddress(&x16Addr, g_X16);
    cudaGetSymbolAddress(&xpAddr,  g_Xp);
    cudaGetSymbolAddress(&wAddr,   g_Wb);

    CUtensorMap tmX16, tmXp, tmW192, tmW64;
    make_map(enc, &tmX16, x16Addr, 4096, 32);
    make_map(enc, &tmXp,  xpAddr,  512,  64);
    make_map(enc, &tmW192, wAddr,  256,  192);
    make_map(enc, &tmW64,  wAddr,  256,  64);

    cudaFuncSetAttribute(gemm_tc_kernel,
                         cudaFuncAttributeMaxDynamicSharedMemorySize, GEMM_SMEM);

    gather_pack_kernel<<<256 + 32, 512>>>(token, kw_idx, q_w, k_w, v_w, mi_w);
    gemm_tc_kernel<<<136, 256, GEMM_SMEM>>>(tmX16, tmXp, tmW192, tmW64);
    head_kernel<<<B_, 256>>>(q_b, k_b, v_b, mi_b, inter_w, inter_b,
                             fc0_w, fc0_b, fc1_w, fc1_b, out);
}

// round 14
// speedup vs baseline: 3.1132x; 1.0861x over previous
#include <cuda_runtime.h>
#include <cuda.h>
#include <cuda_bf16.h>
#include <math.h>
#include <stdint.h>

// Problem constants
#define B_   128
#define S_   256
#define D_   1024
#define K_   8
#define L_   2

// -------- scratch (no allocations allowed) --------
__device__ uint16_t g_X16[(size_t)4096 * D_];  // gathered data rows, bf16
__device__ uint16_t g_Xp [(size_t)512 * D_];   // pooled rows bf16 (bs*2+{max,avg})
__device__ uint16_t g_Wb [(size_t)256 * D_];   // packed weights q|k|v|mi, bf16
__device__ float    g_Ymi [(size_t)512 * 64];  // mi projections
__device__ int      g_miDone;                  // mi-completion flag (reset by gather)

__device__ __forceinline__ uint2 f4_to_bf4(float4 v) {
    __nv_bfloat162 lo = __floats2bfloat162_rn(v.x, v.y);
    __nv_bfloat162 hi = __floats2bfloat162_rn(v.z, v.w);
    uint2 r;
    r.x = *reinterpret_cast<uint32_t*>(&lo);
    r.y = *reinterpret_cast<uint32_t*>(&hi);
    return r;
}

// =====================================================================
// Kernel 1: gather (blocks 0..255, 512 thr) + weight pack (256..287)
//           + g_miDone reset
// =====================================================================
__global__ void __launch_bounds__(512)
gather_pack_kernel(const float* __restrict__ token,
                   const int* __restrict__ kw_idx,
                   const float* __restrict__ wq, const float* __restrict__ wk,
                   const float* __restrict__ wv, const float* __restrict__ wmi)
{
    int tid = threadIdx.x;
    if (blockIdx.x >= 256) {
        if (blockIdx.x == 256 && tid == 0) g_miDone = 0;
        int f4base = (blockIdx.x - 256) * 2048 + tid;
        #pragma unroll
        for (int i = 0; i < 4; i++) {
            int f4 = f4base + i * 512;
            int wsel = f4 >> 14;
            const float* W = (wsel == 0) ? wq : (wsel == 1) ? wk :
                             (wsel == 2) ? wv : wmi;
            float4 v = reinterpret_cast<const float4*>(W)[f4 & 16383];
            reinterpret_cast<uint2*>(g_Wb)[f4] = f4_to_bf4(v);
        }
        return;
    }

    __shared__ int idx[K_];
    __shared__ float4 pmax[2][256];
    __shared__ float4 psum[2][256];

    int bs = blockIdx.x;
    int b = bs >> 1, s = bs & 1;
    if (tid < K_)
        idx[tid] = kw_idx[(b * 2 + (1 - s)) * K_ + tid];
    __syncthreads();

    int col = tid & 255;
    int rp  = tid >> 8;
    const float* tbase = token + (((size_t)b * 2 + s) * L_ + rp) * S_ * D_;
    uint16_t* Xrow = g_X16 + (size_t)bs * 16 * D_;

    float4 mx = make_float4(-3.4e38f, -3.4e38f, -3.4e38f, -3.4e38f);
    float4 sm = make_float4(0.f, 0.f, 0.f, 0.f);

    #pragma unroll
    for (int j = 0; j < 8; j++) {
        int r = rp * 8 + j;
        float4 v = reinterpret_cast<const float4*>(tbase + (size_t)idx[j] * D_)[col];
        reinterpret_cast<uint2*>(Xrow + (size_t)r * D_)[col] = f4_to_bf4(v);
        mx.x = fmaxf(mx.x, v.x); mx.y = fmaxf(mx.y, v.y);
        mx.z = fmaxf(mx.z, v.z); mx.w = fmaxf(mx.w, v.w);
        sm.x += v.x; sm.y += v.y; sm.z += v.z; sm.w += v.w;
    }
    pmax[rp][col] = mx;
    psum[rp][col] = sm;
    __syncthreads();

    if (tid < 256) {
        float4 m0 = pmax[0][col], m1 = pmax[1][col];
        float4 s0 = psum[0][col], s1 = psum[1][col];
        float4 M, S;
        M.x = fmaxf(m0.x, m1.x); M.y = fmaxf(m0.y, m1.y);
        M.z = fmaxf(m0.z, m1.z); M.w = fmaxf(m0.w, m1.w);
        S.x = (s0.x + s1.x) * (1.f/16.f);
        S.y = (s0.y + s1.y) * (1.f/16.f);
        S.z = (s0.z + s1.z) * (1.f/16.f);
        S.w = (s0.w + s1.w) * (1.f/16.f);
        uint16_t* Xp = g_Xp + (size_t)bs * 2 * D_;
        reinterpret_cast<uint2*>(Xp)[col]      = f4_to_bf4(M);
        reinterpret_cast<uint2*>(Xp + D_)[col] = f4_to_bf4(S);
    }
}

// =====================================================================
// Kernel 2: FUSED GEMM + head.
//  blocks 0..7  : mi — 64x64 tile over g_Xp -> g_Ymi, then flag.
//  blocks 8..135: qkv — 32x192 tile (batch b = bid-8) -> head inline.
// TMA SW128 3-stage ring, ldmatrix.x4, mma.m16n8k16 f32acc.
// =====================================================================
#define QA_ST  4096
#define QB_ST  24576
#define QSTG   (QA_ST + QB_ST)        // 28672
#define MA_ST  8192
#define MB_ST  8192
#define MSTG   (MA_ST + MB_ST)
#define GEMM_SMEM (3 * QSTG)          // 86016 dynamic

#define PS 68   // padded head row stride (floats)

__device__ __forceinline__ void mbar_wait(uint32_t mbar, int phase) {
    asm volatile(
        "{\n\t.reg .pred P;\n"
        "W%=:\n\t"
        "mbarrier.try_wait.parity.acquire.cta.shared::cta.b64 P, [%0], %1, 0x989680;\n\t"
        "@P bra D%=;\n\t"
        "bra W%=;\n"
        "D%=:\n\t}"
        :: "r"(mbar), "r"(phase) : "memory");
}

__device__ __forceinline__ void tma_2d(uint32_t dst, const CUtensorMap* tm,
                                       int x, int y, uint32_t mbar) {
    asm volatile(
        "cp.async.bulk.tensor.2d.shared::cta.global.tile.mbarrier::complete_tx::bytes "
        "[%0], [%1, {%2, %3}], [%4];"
        :: "r"(dst), "l"(tm), "r"(x), "r"(y), "r"(mbar) : "memory");
}

#define LDMX4(dst, addr) \
    asm volatile("ldmatrix.sync.aligned.m8n8.x4.shared.b16 {%0,%1,%2,%3}, [%4];" \
                 : "=r"((dst)[0]), "=r"((dst)[1]), "=r"((dst)[2]), "=r"((dst)[3]) : "r"(addr))

#define MMA16816(c, a, b0r, b1r) \
    asm volatile("mma.sync.aligned.m16n8k16.row.col.f32.bf16.bf16.f32 " \
                 "{%0,%1,%2,%3}, {%4,%5,%6,%7}, {%8,%9}, {%0,%1,%2,%3};" \
                 : "+f"((c)[0]), "+f"((c)[1]), "+f"((c)[2]), "+f"((c)[3]) \
                 : "r"((a)[0]), "r"((a)[1]), "r"((a)[2]), "r"((a)[3]), \
                   "r"(b0r), "r"(b1r))

__device__ __forceinline__ float gelu_f(float x) {
    return 0.5f * x * (1.0f + erff(x * 0.70710678118654752440f));
}
__device__ __forceinline__ float4 fma4(float4 a, float4 b, float4 c) {
    return make_float4(fmaf(a.x,b.x,c.x), fmaf(a.y,b.y,c.y),
                       fmaf(a.z,b.z,c.z), fmaf(a.w,b.w,c.w));
}
__device__ __forceinline__ float hsum4(float4 a) { return (a.x+a.y)+(a.z+a.w); }

__global__ void __launch_bounds__(256, 1)
gemm_head_kernel(const __grid_constant__ CUtensorMap tmX16,
                 const __grid_constant__ CUtensorMap tmXp,
                 const __grid_constant__ CUtensorMap tmW192,
                 const __grid_constant__ CUtensorMap tmW64,
                 const float* __restrict__ q_b, const float* __restrict__ k_b,
                 const float* __restrict__ v_b, const float* __restrict__ mi_b,
                 const float* __restrict__ inter_w, const float* __restrict__ inter_b,
                 const float* __restrict__ fc0_w, const float* __restrict__ fc0_b,
                 const float* __restrict__ fc1_w, const float* __restrict__ fc1_b,
                 float* __restrict__ out)
{
    extern __shared__ __align__(1024) uint16_t smem_b[];
    __shared__ __align__(8) uint64_t mbar_s[6];
    // head smem: hbuf[(bs_local*3 + which)*16 + n][PS]  (q0,k0,v0,q1,k1,v1)
    __shared__ __align__(16) float hbuf[6 * 16 * PS];
    __shared__ __align__(16) float e1s[16*PS], e2s[16*PS];
    __shared__ __align__(16) float att[512];
    __shared__ __align__(16) float sv[4][64];
    __shared__ __align__(16) float aV[4][64];
    __shared__ __align__(16) float feat[520];
    __shared__ float h1[64];

    const uint32_t smem_s = (uint32_t)__cvta_generic_to_shared(smem_b);
    const uint32_t mb     = (uint32_t)__cvta_generic_to_shared(mbar_s);

    const int tid  = threadIdx.x;
    const int lane = tid & 31;
    const int warp = tid >> 5;
    const bool isMi = (blockIdx.x < 8);

    if (tid == 0) {
        #pragma unroll
        for (int s = 0; s < 3; s++) {
            asm volatile("mbarrier.init.shared.b64 [%0], %1;" :: "r"(mb + s * 8), "r"(1) : "memory");
            asm volatile("mbarrier.init.shared.b64 [%0], %1;" :: "r"(mb + 24 + s * 8), "r"(256) : "memory");
        }
    }
    __syncthreads();

    const int j4 = lane >> 3;
    const int lr = lane & 7;
    const int g  = lane >> 2;
    const int tg = lane & 3;

    if (isMi) {
        // ---------- mi: 64x64 tile over pooled rows ----------
        const int m0 = blockIdx.x * 64;
        const int wm = warp >> 2;
        const int wn = warp & 3;

        if (tid == 0) {
            #pragma unroll
            for (int s = 0; s < 3; s++) {
                uint32_t fb = mb + s * 8;
                asm volatile("mbarrier.arrive.expect_tx.shared.b64 _, [%0], %1;"
                             :: "r"(fb), "r"(MSTG) : "memory");
                uint32_t base = smem_s + s * MSTG;
                tma_2d(base,         &tmXp, s * 64, m0, fb);
                tma_2d(base + MA_ST, &tmW64, s * 64, 192, fb);
            }
        }

        float c[2][2][4];
        #pragma unroll
        for (int i = 0; i < 2; i++)
            #pragma unroll
            for (int j = 0; j < 2; j++)
                #pragma unroll
                for (int r = 0; r < 4; r++) c[i][j][r] = 0.f;

        const int aRow = wm * 32 + (j4 & 1) * 8 + lr;
        const int aKj  = j4 >> 1;
        const int aSw  = aRow & 7;
        const uint32_t aByte0 = aRow * 128;
        const uint32_t aByte1 = (aRow + 16) * 128;
        const int bRow = wn * 16 + (j4 >> 1) * 8 + lr;
        const int bKj  = j4 & 1;
        const int bSw  = bRow & 7;
        const uint32_t bByte = bRow * 128;

        int cs = 0, cph = 0, ps = 0, pep = 0;
        for (int kt = 0; kt < 16; kt++) {
            mbar_wait(mb + cs * 8, cph);
            const uint32_t As = smem_s + cs * MSTG;
            const uint32_t Bs = As + MA_ST;

            #pragma unroll
            for (int step = 0; step < 4; step++) {
                const int cA = (2 * step + aKj) ^ aSw;
                const int cB = (2 * step + bKj) ^ bSw;
                uint32_t a0[4], a1[4], bb[4];
                LDMX4(a0, As + aByte0 + (cA << 4));
                LDMX4(a1, As + aByte1 + (cA << 4));
                LDMX4(bb, Bs + bByte + (cB << 4));
                #pragma unroll
                for (int mt = 0; mt < 2; mt++) {
                    const uint32_t* a = mt ? a1 : a0;
                    #pragma unroll
                    for (int nt = 0; nt < 2; nt++)
                        MMA16816(c[mt][nt], a, bb[nt*2], bb[nt*2+1]);
                }
            }

            asm volatile("mbarrier.arrive.shared.b64 _, [%0];" :: "r"(mb + 24 + cs * 8) : "memory");

            if (tid == 0 && kt + 3 < 16) {
                mbar_wait(mb + 24 + ps * 8, pep);
                uint32_t fb = mb + ps * 8;
                asm volatile("mbarrier.arrive.expect_tx.shared.b64 _, [%0], %1;"
                             :: "r"(fb), "r"(MSTG) : "memory");
                uint32_t base = smem_s + ps * MSTG;
                tma_2d(base,         &tmXp, (kt + 3) * 64, m0, fb);
                tma_2d(base + MA_ST, &tmW64, (kt + 3) * 64, 192, fb);
                ps++; if (ps == 3) { ps = 0; pep ^= 1; }
            }
            cs++; if (cs == 3) { cs = 0; cph ^= 1; }
        }

        #pragma unroll
        for (int mt = 0; mt < 2; mt++) {
            const int rA = m0 + wm * 32 + mt * 16 + g;
            #pragma unroll
            for (int nt = 0; nt < 2; nt++) {
                const int col = wn * 16 + nt * 8 + 2 * tg;
                *reinterpret_cast<float2*>(g_Ymi + (size_t)rA * 64 + col) =
                    make_float2(c[mt][nt][0], c[mt][nt][1]);
                *reinterpret_cast<float2*>(g_Ymi + (size_t)(rA + 8) * 64 + col) =
                    make_float2(c[mt][nt][2], c[mt][nt][3]);
            }
        }
        __syncthreads();
        if (tid == 0) {
            __threadfence();
            atomicAdd(&g_miDone, 1);
        }
        return;
    }

    // ---------- qkv: 32x192 tile + inline head (batch b = bid-8) ----------
    const int b  = blockIdx.x - 8;
    const int m0 = b * 32;
    const int wm = warp >> 2;      // 0..1 -> bs_local
    const int wn = warp & 3;       // 0..3 (48 cols)

    if (tid == 0) {
        #pragma unroll
        for (int s = 0; s < 3; s++) {
            uint32_t fb = mb + s * 8;
            asm volatile("mbarrier.arrive.expect_tx.shared.b64 _, [%0], %1;"
                         :: "r"(fb), "r"(QSTG) : "memory");
            uint32_t base = smem_s + s * QSTG;
            tma_2d(base,         &tmX16, s * 64, m0, fb);
            tma_2d(base + QA_ST, &tmW192, s * 64, 0, fb);
        }
    }

    float c[6][4];
    #pragma unroll
    for (int j = 0; j < 6; j++)
        #pragma unroll
        for (int r = 0; r < 4; r++) c[j][r] = 0.f;

    const int aRow = wm * 16 + (j4 & 1) * 8 + lr;
    const int aKj  = j4 >> 1;
    const int aSw  = aRow & 7;
    const uint32_t aByte = aRow * 128;
    const int bKj  = j4 & 1;
    const int bSw  = lr;
    uint32_t bByte[3];
    #pragma unroll
    for (int t = 0; t < 3; t++)
        bByte[t] = (wn * 48 + t * 16 + (j4 >> 1) * 8 + lr) * 128;

    int cs = 0, cph = 0, ps = 0, pep = 0;
    for (int kt = 0; kt < 16; kt++) {
        mbar_wait(mb + cs * 8, cph);
        const uint32_t As = smem_s + cs * QSTG;
        const uint32_t Bs = As + QA_ST;

        #pragma unroll
        for (int step = 0; step < 4; step++) {
            const int cA = (2 * step + aKj) ^ aSw;
            const int cB = (2 * step + bKj) ^ bSw;
            uint32_t a[4], bfr[3][4];
            LDMX4(a, As + aByte + (cA << 4));
            #pragma unroll
            for (int t = 0; t < 3; t++)
                LDMX4(bfr[t], Bs + bByte[t] + (cB << 4));
            #pragma unroll
            for (int nt = 0; nt < 6; nt++) {
                const uint32_t* bb = &bfr[nt >> 1][(nt & 1) * 2];
                MMA16816(c[nt], a, bb[0], bb[1]);
            }
        }

        asm volatile("mbarrier.arrive.shared.b64 _, [%0];" :: "r"(mb + 24 + cs * 8) : "memory");

        if (tid == 0 && kt + 3 < 16) {
            mbar_wait(mb + 24 + ps * 8, pep);
            uint32_t fb = mb + ps * 8;
            asm volatile("mbarrier.arrive.expect_tx.shared.b64 _, [%0], %1;"
                         :: "r"(fb), "r"(QSTG) : "memory");
            uint32_t base = smem_s + ps * QSTG;
            tma_2d(base,         &tmX16, (kt + 3) * 64, m0, fb);
            tma_2d(base + QA_ST, &tmW192, (kt + 3) * 64, 0, fb);
            ps++; if (ps == 3) { ps = 0; pep ^= 1; }
        }
        cs++; if (cs == 3) { cs = 0; cph ^= 1; }
    }

    // ---- epilogue: accumulators + bias -> head smem ----
    #pragma unroll
    for (int nt = 0; nt < 6; nt++) {
        const int col   = wn * 48 + nt * 8 + 2 * tg;
        const int which = col >> 6;
        const int hcol  = col & 63;
        const float* bp = (which == 0) ? q_b : (which == 1) ? k_b : v_b;
        float b0 = bp[hcol], b1 = bp[hcol + 1];
        float* d0 = hbuf + (size_t)((wm * 3 + which) * 16 + g) * PS + hcol;
        float* d1 = d0 + 8 * PS;
        d0[0] = c[nt][0] + b0; d0[1] = c[nt][1] + b1;
        d1[0] = c[nt][2] + b0; d1[1] = c[nt][3] + b1;
    }

    // ---- wait for mi results ----
    if (tid == 0) {
        int v;
        do {
            asm volatile("ld.global.acquire.gpu.b32 %0, [%1];" : "=r"(v) : "l"(&g_miDone));
        } while (v < 8);
    }
    __syncthreads();

    const float* q0 = hbuf + 0 * 16 * PS;
    const float* k0 = hbuf + 1 * 16 * PS;
    const float* v0 = hbuf + 2 * 16 * PS;
    const float* q1 = hbuf + 3 * 16 * PS;
    const float* k1 = hbuf + 4 * 16 * PS;
    const float* v1 = hbuf + 5 * 16 * PS;

    {
        int i = tid >> 6, h = tid & 63;
        sv[i][h] = g_Ymi[(size_t)(b * 4 + i) * 64 + h] + mi_b[h];
    }
    __syncthreads();

    // att + inter
    #pragma unroll
    for (int e = tid; e < 512; e += 256) {
        int which = e >> 8, n = (e >> 4) & 15, m = e & 15;
        const float4* qq = reinterpret_cast<const float4*>((which ? q1 : q0) + n * PS);
        const float4* kk = reinterpret_cast<const float4*>((which ? k0 : k1) + m * PS);
        float4 acc = make_float4(0,0,0,0);
        #pragma unroll
        for (int t = 0; t < 16; t++) acc = fma4(qq[t], kk[t], acc);
        att[e] = hsum4(acc) * 0.125f;
    }
    {
        int i = tid >> 6, j = tid & 63;
        const float4* w = reinterpret_cast<const float4*>(inter_w + ((size_t)i * 64 + j) * 64);
        const float4* src = reinterpret_cast<const float4*>(sv[i >> 1]);
        float4 acc = make_float4(0,0,0,0);
        #pragma unroll
        for (int t = 0; t < 16; t++) acc = fma4(w[t], src[t], acc);
        aV[i][j] = inter_b[i * 64 + j] + hsum4(acc);
    }
    __syncthreads();

    // e = att @ v + cosines
    #pragma unroll
    for (int f = tid; f < 512; f += 256) {
        int which = f >> 8, n = (f >> 4) & 15, h4 = f & 15;
        const float* vv = which ? v0 : v1;
        const float* am = att + which * 256 + n * 16;
        float4 s = make_float4(0,0,0,0);
        #pragma unroll
        for (int m = 0; m < 16; m++) {
            float a = am[m];
            float4 vm = *reinterpret_cast<const float4*>(vv + m * PS + 4 * h4);
            s.x = fmaf(a, vm.x, s.x); s.y = fmaf(a, vm.y, s.y);
            s.z = fmaf(a, vm.z, s.z); s.w = fmaf(a, vm.w, s.w);
        }
        *reinterpret_cast<float4*>((which ? e2s : e1s) + n * PS + 4 * h4) = s;
    }
    if (tid < 4) {
        int i = tid;
        const float4* av = reinterpret_cast<const float4*>(aV[i]);
        const float4* bv = reinterpret_cast<const float4*>(sv[2 + (i & 1)]);
        float4 d4 = make_float4(0,0,0,0), a4 = d4, b4 = d4;
        #pragma unroll
        for (int t = 0; t < 16; t++) {
            float4 a = av[t], bb = bv[t];
            d4 = fma4(a, bb, d4); a4 = fma4(a, a, a4); b4 = fma4(bb, bb, b4);
        }
        float na = fmaxf(sqrtf(hsum4(a4)), 1e-8f);
        float nb = fmaxf(sqrtf(hsum4(b4)), 1e-8f);
        feat[256 + i] = hsum4(d4) / (na * nb);
    }
    __syncthreads();

    if (tid < 128) {
        int which = tid >> 6, hh = tid & 63;
        const float* E = which ? e2s : e1s;
        float mx = -3.4e38f, sm = 0.f;
        #pragma unroll
        for (int n = 0; n < 16; n++) { float v = E[n * PS + hh]; mx = fmaxf(mx, v); sm += v; }
        feat[which * 128 + hh]      = mx;
        feat[which * 128 + 64 + hh] = sm * (1.f / 16.f);
    }
    feat[260 + tid] = sv[tid >> 6][tid & 63];
    __syncthreads();

    {
        int j = tid >> 2, part = tid & 3;
        int off = part * 128;
        int n4 = (part == 3) ? 33 : 32;
        const float4* w  = reinterpret_cast<const float4*>(fc0_w + (size_t)j * 516 + off);
        const float4* fr = reinterpret_cast<const float4*>(feat + off);
        float4 acc = make_float4(0,0,0,0);
        #pragma unroll 8
        for (int t = 0; t < n4; t++) acc = fma4(w[t], fr[t], acc);
        float s = hsum4(acc);
        s += __shfl_xor_sync(0xffffffff, s, 1);
        s += __shfl_xor_sync(0xffffffff, s, 2);
        if (part == 0) h1[j] = gelu_f(fc0_b[j] + s);
    }
    __syncthreads();

    if (tid == 0) {
        float l0 = fc1_b[0], l1 = fc1_b[1];
        #pragma unroll
        for (int j = 0; j < 64; j++) { l0 += h1[j] * fc1_w[j]; l1 += h1[j] * fc1_w[64 + j]; }
        l0 = gelu_f(l0); l1 = gelu_f(l1);
        float m = fmaxf(l0, l1);
        float ea = expf(l0 - m), eb = expf(l1 - m);
        float inv = 1.f / (ea + eb);
        out[b * 2 + 0] = ea * inv;
        out[b * 2 + 1] = eb * inv;
    }
}

// =====================================================================
typedef CUresult (*EncodeTiledFn)(
    CUtensorMap*, CUtensorMapDataType, cuuint32_t, void*,
    const cuuint64_t*, const cuuint64_t*, const cuuint32_t*, const cuuint32_t*,
    CUtensorMapInterleave, CUtensorMapSwizzle, CUtensorMapL2promotion,
    CUtensorMapFloatOOBfill);

static void make_map(EncodeTiledFn enc, CUtensorMap* tm, void* addr,
                     unsigned rows, unsigned boxRows) {
    cuuint64_t dims[2]    = {D_, rows};
    cuuint64_t strides[1] = {D_ * 2};
    cuuint32_t box[2]     = {64, boxRows};
    cuuint32_t es[2]      = {1, 1};
    enc(tm, CU_TENSOR_MAP_DATA_TYPE_BFLOAT16, 2, addr,
        dims, strides, box, es,
        CU_TENSOR_MAP_INTERLEAVE_NONE, CU_TENSOR_MAP_SWIZZLE_128B,
        CU_TENSOR_MAP_L2_PROMOTION_L2_128B, CU_TENSOR_MAP_FLOAT_OOB_FILL_NONE);
}

extern "C" void kernel_launch(void* const* d_in, const int* in_sizes, int n_in,
                              void* d_out, int out_size)
{
    const float* token   = (const float*)d_in[0];
    const int*   kw_idx  = (const int*)  d_in[1];
    const float* q_w     = (const float*)d_in[2];
    const float* q_b     = (const float*)d_in[3];
    const float* k_w     = (const float*)d_in[4];
    const float* k_b     = (const float*)d_in[5];
    const float* v_w     = (const float*)d_in[6];
    const float* v_b     = (const float*)d_in[7];
    const float* mi_w    = (const float*)d_in[8];
    const float* mi_b    = (const float*)d_in[9];
    const float* inter_w = (const float*)d_in[10];
    const float* inter_b = (const float*)d_in[11];
    const float* fc0_w   = (const float*)d_in[12];
    const float* fc0_b   = (const float*)d_in[13];
    const float* fc1_w   = (const float*)d_in[14];
    const float* fc1_b   = (const float*)d_in[15];
    float* out = (float*)d_out;

    void* encPtr = nullptr;
    cudaDriverEntryPointQueryResult qr;
    cudaGetDriverEntryPointByVersion("cuTensorMapEncodeTiled", &encPtr, 12000,
                                     cudaEnableDefault, &qr);
    EncodeTiledFn enc = (EncodeTiledFn)encPtr;

    void *x16Addr = nullptr, *xpAddr = nullptr, *wAddr = nullptr;
    cudaGetSymbolAddress(&x16Addr, g_X16);
    cudaGetSymbolAddress(&xpAddr,  g_Xp);
    cudaGetSymbolAddress(&wAddr,   g_Wb);

    CUtensorMap tmX16, tmXp, tmW192, tmW64;
    make_map(enc, &tmX16, x16Addr, 4096, 32);
    make_map(enc, &tmXp,  xpAddr,  512,  64);
    make_map(enc, &tmW192, wAddr,  256,  192);
    make_map(enc, &tmW64,  wAddr,  256,  64);

    cudaFuncSetAttribute(gemm_head_kernel,
                         cudaFuncAttributeMaxDynamicSharedMemorySize, GEMM_SMEM);

    gather_pack_kernel<<<256 + 32, 512>>>(token, kw_idx, q_w, k_w, v_w, mi_w);
    gemm_head_kernel<<<136, 256, GEMM_SMEM>>>(tmX16, tmXp, tmW192, tmW64,
                                              q_b, k_b, v_b, mi_b,
                                              inter_w, inter_b,
                                              fc0_w, fc0_b, fc1_w, fc1_b, out);
}